// round 10
// baseline (speedup 1.0000x reference)
#include <cuda_runtime.h>

#define PLANES 48  // B*C = 16*3

// ---------------- static device scratch (no allocations allowed) ----------------
__device__ float g_d1[2][PLANES * 256 * 256];  // level-0 downs == level-1 currents
__device__ float g_d2[2][PLANES * 128 * 128];  // level-1 downs == level-2 currents
__device__ double g_acc[3];                    // per-level |.| sums

// reflect index (numpy 'reflect', pad<=2): -1->1, -2->2, n->n-2, n+1->n-3
__device__ __forceinline__ int refl(int p, int n) {
    p = (p < 0) ? -p : p;
    return (p >= n) ? (2 * n - 2 - p) : p;
}

__global__ void zero_acc_kernel() {
    if (threadIdx.x < 3) g_acc[threadIdx.x] = 0.0;
}

// -------------------------------------------------------------------------------
// lap_kernel<LVL>: fused down+up+diff+sobel+reduce, one kernel per level.
// block (32,16)=512 threads; per block: 32x64 tile of the (N+2)x(N+2) loss grid.
// Interior blocks (no reflection) take a fully-linear vectorized path.
// -------------------------------------------------------------------------------
template <int LVL>
__global__ __launch_bounds__(512) void lap_kernel(const float* __restrict__ extA,
                                                  const float* __restrict__ extB) {
    constexpr int N  = (LVL == 0) ? 512 : (LVL == 1) ? 256 : 128;
    constexpr int N2 = N >> 1;

    const int p = blockIdx.z;
    const float *cur0, *cur1;
    float *dn0 = nullptr, *dn1 = nullptr;
    if constexpr (LVL == 0) {
        cur0 = extA + (size_t)p * N * N;     cur1 = extB + (size_t)p * N * N;
        dn0 = g_d1[0] + (size_t)p * N2 * N2; dn1 = g_d1[1] + (size_t)p * N2 * N2;
    } else if constexpr (LVL == 1) {
        cur0 = g_d1[0] + (size_t)p * N * N;  cur1 = g_d1[1] + (size_t)p * N * N;
        dn0 = g_d2[0] + (size_t)p * N2 * N2; dn1 = g_d2[1] + (size_t)p * N2 * N2;
    } else {
        cur0 = g_d2[0] + (size_t)p * N * N;  cur1 = g_d2[1] + (size_t)p * N * N;
    }

    __shared__ __align__(16) float s_cur[43][80];    // reflected cur tile
    __shared__ __align__(16) float s_dw[20][40];     // down window
    __shared__ __align__(16) float s_h[20][68];      // horizontally upsampled rows
    __shared__ __align__(16) float s_df[2][34][68];  // diff tiles (also phase-B scratch)
    __shared__ int rowoffT[43], colmapT[77];
    __shared__ int shi[34], riT[34][3];
    __shared__ float rwT[34][3];
    __shared__ int swj[66], ciT[66][3];
    __shared__ float cwT[66][3];
    __shared__ float warpsum[16];

    const int tx = threadIdx.x, ty = threadIdx.y;
    const int tid = ty * 32 + tx;
    const int oy0 = blockIdx.y * 32, ox0 = blockIdx.x * 64;
    const int R0 = max(0, (oy0 - 4) >> 1);
    const int C0 = max(0, (ox0 - 4) >> 1);
    const int gr0 = 2 * R0 - 2;   // cur tile global row 0
    const int gc0 = 2 * C0 - 2;   // cur tile global col 0

    const bool interior = (gr0 >= 0) && (gr0 + 42 <= N - 1)
                       && (gc0 >= 0) && (gc0 + 77 <= N - 1);

    // ---- boundary-only tables ----
    if (!interior) {
        if (tid < 43) {
            rowoffT[tid] = refl(gr0 + tid, N) * N;
        } else if (tid < 120) {
            colmapT[tid - 43] = refl(gc0 + tid - 43, N);
        } else if (tid < 154) {
            const int i = tid - 120;
            const int h = refl(oy0 - 2 + i, N);
            shi[i] = min(max(h - gr0, 0), 42);
            int a, b, c; float x, y, z;
            if (h & 1) { a = refl(h - 1, N) >> 1; b = refl(h + 1, N) >> 1; c = a;
                         x = 0.5f; y = 0.5f; z = 0.f; }
            else       { a = refl(h - 2, N) >> 1; b = h >> 1; c = refl(h + 2, N) >> 1;
                         x = 0.125f; y = 0.75f; z = 0.125f; }
            riT[i][0] = min(max(a - R0, 0), 19);
            riT[i][1] = min(max(b - R0, 0), 19);
            riT[i][2] = min(max(c - R0, 0), 19);
            rwT[i][0] = x; rwT[i][1] = y; rwT[i][2] = z;
        } else if (tid < 220) {
            const int j = tid - 154;
            const int w = refl(ox0 - 2 + j, N);
            swj[j] = min(max(w - gc0, 0), 76);
            int a, b, c; float x, y, z;
            if (w & 1) { a = refl(w - 1, N) >> 1; b = refl(w + 1, N) >> 1; c = a;
                         x = 0.5f; y = 0.5f; z = 0.f; }
            else       { a = refl(w - 2, N) >> 1; b = w >> 1; c = refl(w + 2, N) >> 1;
                         x = 0.125f; y = 0.75f; z = 0.125f; }
            ciT[j][0] = min(max(a - C0, 0), 36);
            ciT[j][1] = min(max(b - C0, 0), 36);
            ciT[j][2] = min(max(c - C0, 0), 36);
            cwT[j][0] = x; cwT[j][1] = y; cwT[j][2] = z;
        }
        __syncthreads();
    }

    for (int img = 0; img < 2; img++) {
        const float* cur = img ? cur1 : cur0;
        float* s_t = &s_df[img][0][0];   // phase-B scratch (pitch 80), dead until D

        // ---- A: load cur tile into smem ----
        if (interior) {
#pragma unroll
            for (int r = ty; r < 43; r += 16) {
                const float* rp = cur + (gr0 + r) * N + gc0;
#pragma unroll
                for (int c = 2 * tx; c < 78; c += 64)
                    *(float2*)&s_cur[r][c] = *(const float2*)(rp + c);
            }
        } else {
#pragma unroll
            for (int r = ty; r < 43; r += 16) {
                const int ro = rowoffT[r];
#pragma unroll
                for (int c = tx; c < 77; c += 32)
                    s_cur[r][c] = __ldg(&cur[ro + colmapT[c]]);
            }
        }
        __syncthreads();

        // ---- B1: vertical 5-tap [1,4,6,4,1] at down rows (float4) ----
#pragma unroll
        for (int r = ty; r < 20; r += 16) {
            if (tx < 20) {
                const int rs = 2 * r, c4 = 4 * tx;
                float4 a0 = *(const float4*)&s_cur[rs + 0][c4];
                float4 a1 = *(const float4*)&s_cur[rs + 1][c4];
                float4 a2 = *(const float4*)&s_cur[rs + 2][c4];
                float4 a3 = *(const float4*)&s_cur[rs + 3][c4];
                float4 a4 = *(const float4*)&s_cur[rs + 4][c4];
                float4 o;
                o.x = a0.x + 4.f * (a1.x + a3.x) + 6.f * a2.x + a4.x;
                o.y = a0.y + 4.f * (a1.y + a3.y) + 6.f * a2.y + a4.y;
                o.z = a0.z + 4.f * (a1.z + a3.z) + 6.f * a2.z + a4.z;
                o.w = a0.w + 4.f * (a1.w + a3.w) + 6.f * a2.w + a4.w;
                *(float4*)&s_t[r * 80 + c4] = o;
            }
        }
        __syncthreads();

        // ---- B2: horizontal 5-tap at stride-2 -> down window (2 outputs/thread) ----
#pragma unroll
        for (int r = ty; r < 20; r += 16) {
            if (tx < 19) {
                const float* t = &s_t[r * 80 + 4 * tx];
                float4 q0 = *(const float4*)t;
                float4 q1 = *(const float4*)(t + 4);
                float o0 = (q0.x + 4.f * q0.y + 6.f * q0.z + 4.f * q0.w + q1.x)
                         * (1.0f / 256.0f);
                float o1 = (q0.z + 4.f * q0.w + 6.f * q1.x + 4.f * q1.y + q1.z)
                         * (1.0f / 256.0f);
                *(float2*)&s_dw[r][2 * tx] = make_float2(o0, o1);
            }
        }
        __syncthreads();

        // ---- B3: write block-owned 16x32 down piece for the next level ----
        if constexpr (LVL < 2) {
            const int bi = blockIdx.y, bj = blockIdx.x;
            if (bi < (N2 >> 4) && bj < (N2 >> 5)) {
                float* dn = img ? dn1 : dn0;
                dn[(size_t)((bi << 4) + ty) * N2 + (bj << 5) + tx] =
                    s_dw[(bi << 4) - R0 + ty][(bj << 5) - C0 + tx];
            }
        }

        // ---- C: horizontal up pass over down rows ----
        if (interior) {
#pragma unroll
            for (int r = ty; r < 20; r += 16) {
#pragma unroll
                for (int q = tx; q < 33; q += 32) {
                    float a = s_dw[r][q], b = s_dw[r][q + 1], c = s_dw[r][q + 2];
                    float e = 0.125f * a + 0.75f * b + 0.125f * c;  // even j=2q
                    float o = 0.5f * (b + c);                        // odd j=2q+1
                    *(float2*)&s_h[r][2 * q] = make_float2(e, o);
                }
            }
        } else {
#pragma unroll
            for (int r = ty; r < 20; r += 16) {
#pragma unroll
                for (int j = tx; j < 66; j += 32)
                    s_h[r][j] = cwT[j][0] * s_dw[r][ciT[j][0]]
                              + cwT[j][1] * s_dw[r][ciT[j][1]]
                              + cwT[j][2] * s_dw[r][ciT[j][2]];
            }
        }
        __syncthreads();

        // ---- D: vertical up pass + diff (cur from smem) ----
        if (interior) {
#pragma unroll
            for (int i = ty; i < 34; i += 16) {
                int a, b, c; float w0, w1, w2;
                if (i & 1) { a = (i + 1) >> 1; b = (i + 3) >> 1; c = a;
                             w0 = 0.5f; w1 = 0.5f; w2 = 0.f; }
                else       { a = i >> 1; b = a + 1; c = a + 2;
                             w0 = 0.125f; w1 = 0.75f; w2 = 0.125f; }
#pragma unroll
                for (int q = tx; q < 33; q += 32) {
                    const int j = 2 * q;
                    float2 ha = *(const float2*)&s_h[a][j];
                    float2 hb = *(const float2*)&s_h[b][j];
                    float2 hc = *(const float2*)&s_h[c][j];
                    float2 cu = *(const float2*)&s_cur[i + 4][j + 4];
                    float2 o;
                    o.x = cu.x - (w0 * ha.x + w1 * hb.x + w2 * hc.x);
                    o.y = cu.y - (w0 * ha.y + w1 * hb.y + w2 * hc.y);
                    *(float2*)&s_df[img][i][j] = o;
                }
            }
        } else {
#pragma unroll
            for (int i = ty; i < 34; i += 16) {
                const float w0 = rwT[i][0], w1 = rwT[i][1], w2 = rwT[i][2];
                const int a = riT[i][0], b = riT[i][1], cix = riT[i][2];
                const int hs = shi[i];
#pragma unroll
                for (int j = tx; j < 66; j += 32)
                    s_df[img][i][j] = s_cur[hs][swj[j]]
                        - (w0 * s_h[a][j] + w1 * s_h[b][j] + w2 * s_h[cix][j]);
            }
        }
        __syncthreads();
    }

    // ---- E: sobel |GX|+|GY| per image, |m0-m1|; each thread owns a 1x4 strip ----
    float val = 0.f;
    {
        const int row = tid >> 4;        // 0..31
        const int c0  = (tid & 15) << 2; // 0,4,..,60
        const bool rowok = (oy0 + row) < N + 2;
        float m0[4];
#pragma unroll
        for (int im = 0; im < 2; im++) {
            float d0[6], d1[6], d2[6];
#pragma unroll
            for (int rr = 0; rr < 3; rr++) {
                float* dst = (rr == 0) ? d0 : (rr == 1) ? d1 : d2;
                const float4 a = *(const float4*)&s_df[im][row + rr][c0];
                const float2 b = *(const float2*)&s_df[im][row + rr][c0 + 4];
                dst[0] = a.x; dst[1] = a.y; dst[2] = a.z; dst[3] = a.w;
                dst[4] = b.x; dst[5] = b.y;
            }
            float v[6], u[6];
#pragma unroll
            for (int j = 0; j < 6; j++) {
                v[j] = 2.f * d0[j] + 4.f * d1[j] + 2.f * d2[j];
                u[j] = 2.f * (d0[j] - d2[j]);
            }
#pragma unroll
            for (int k = 0; k < 4; k++) {
                float gx = v[k] - v[k + 2];
                float gy = u[k] + 2.f * u[k + 1] + u[k + 2];
                float m = fabsf(gx) + fabsf(gy);
                if (im == 0) m0[k] = m;
                else if (rowok && (ox0 + c0 + k) < N + 2)
                    val += fabsf(m0[k] - m);
            }
        }
    }

    // ---- block reduction -> one double atomic per block ----
#pragma unroll
    for (int off = 16; off > 0; off >>= 1)
        val += __shfl_down_sync(0xffffffffu, val, off);
    if ((tid & 31) == 0) warpsum[tid >> 5] = val;
    __syncthreads();
    if (tid < 16) {
        float v = warpsum[tid];
#pragma unroll
        for (int off = 8; off > 0; off >>= 1)
            v += __shfl_down_sync(0xffffu, v, off);
        if (tid == 0) atomicAdd(&g_acc[LVL], (double)v);
    }
}

__global__ void finalize_kernel(float* __restrict__ out) {
    double l = g_acc[0] / ((double)PLANES * 514.0 * 514.0)
             + g_acc[1] / ((double)PLANES * 258.0 * 258.0)
             + g_acc[2] / ((double)PLANES * 130.0 * 130.0);
    out[0] = (float)l;
}

// -------------------------------------------------------------------------------
extern "C" void kernel_launch(void* const* d_in, const int* in_sizes, int n_in,
                              void* d_out, int out_size) {
    const float* inp = (const float*)d_in[0];
    const float* tgt = (const float*)d_in[1];
    // d_in[2] (gauss_kernel) is a fixed constant — baked into the kernels.
    float* out = (float*)d_out;

    zero_acc_kernel<<<1, 32>>>();

    lap_kernel<0><<<dim3(9, 17, PLANES), dim3(32, 16)>>>(inp, tgt);  // N=512
    lap_kernel<1><<<dim3(5, 9, PLANES),  dim3(32, 16)>>>(inp, tgt);  // N=256
    lap_kernel<2><<<dim3(3, 5, PLANES),  dim3(32, 16)>>>(inp, tgt);  // N=128

    finalize_kernel<<<1, 1>>>(out);
}

// round 11
// speedup vs baseline: 1.2713x; 1.2713x over previous
#include <cuda_runtime.h>

#define PLANES 48  // B*C = 16*3

// ---------------- static device scratch (no allocations allowed) ----------------
__device__ float g_d1[2][PLANES * 256 * 256];  // level-0 downs == level-1 currents
__device__ float g_d2[2][PLANES * 128 * 128];  // level-1 downs == level-2 currents
__device__ double g_acc[3];                    // per-level |.| sums

// reflect index (numpy 'reflect', pad<=2): -1->1, -2->2, n->n-2, n+1->n-3
__device__ __forceinline__ int refl(int p, int n) {
    p = (p < 0) ? -p : p;
    return (p >= n) ? (2 * n - 2 - p) : p;
}

__global__ void zero_acc_kernel() {
    if (threadIdx.x < 3) g_acc[threadIdx.x] = 0.0;
}

// -------------------------------------------------------------------------------
// lap_kernel<LVL>: fused down+up+diff+sobel+reduce, one kernel per level.
// block (32,16)=512 threads; per block: 32x64 tile of the (N+2)x(N+2) loss grid.
// Interior blocks (no reflection) take a fully-linear vectorized path.
// __launch_bounds__(512,4): 4 blocks/SM (32 regs) — occupancy is the binding
// resource per R9 post-mortem.
// -------------------------------------------------------------------------------
template <int LVL>
__global__ __launch_bounds__(512, 4) void lap_kernel(const float* __restrict__ extA,
                                                     const float* __restrict__ extB) {
    constexpr int N  = (LVL == 0) ? 512 : (LVL == 1) ? 256 : 128;
    constexpr int N2 = N >> 1;

    const int p = blockIdx.z;
    const float *cur0, *cur1;
    float *dn0 = nullptr, *dn1 = nullptr;
    if constexpr (LVL == 0) {
        cur0 = extA + (size_t)p * N * N;     cur1 = extB + (size_t)p * N * N;
        dn0 = g_d1[0] + (size_t)p * N2 * N2; dn1 = g_d1[1] + (size_t)p * N2 * N2;
    } else if constexpr (LVL == 1) {
        cur0 = g_d1[0] + (size_t)p * N * N;  cur1 = g_d1[1] + (size_t)p * N * N;
        dn0 = g_d2[0] + (size_t)p * N2 * N2; dn1 = g_d2[1] + (size_t)p * N2 * N2;
    } else {
        cur0 = g_d2[0] + (size_t)p * N * N;  cur1 = g_d2[1] + (size_t)p * N * N;
    }

    __shared__ __align__(16) float s_cur[43][80];    // reflected cur tile
    __shared__ __align__(16) float s_dw[20][40];     // down window
    __shared__ __align__(16) float s_h[20][68];      // horizontally upsampled rows
    __shared__ __align__(16) float s_df[2][34][68];  // diff tiles (also phase-B scratch)
    __shared__ int rowoffT[43], colmapT[77];
    __shared__ int shi[34], riT[34][3];
    __shared__ float rwT[34][3];
    __shared__ int swj[66], ciT[66][3];
    __shared__ float cwT[66][3];
    __shared__ float warpsum[16];

    const int tx = threadIdx.x, ty = threadIdx.y;
    const int tid = ty * 32 + tx;
    const int oy0 = blockIdx.y * 32, ox0 = blockIdx.x * 64;
    const int R0 = max(0, (oy0 - 4) >> 1);
    const int C0 = max(0, (ox0 - 4) >> 1);
    const int gr0 = 2 * R0 - 2;   // cur tile global row 0
    const int gc0 = 2 * C0 - 2;   // cur tile global col 0

    const bool interior = (gr0 >= 0) && (gr0 + 42 <= N - 1)
                       && (gc0 >= 0) && (gc0 + 77 <= N - 1);

    // ---- boundary-only tables ----
    if (!interior) {
        if (tid < 43) {
            rowoffT[tid] = refl(gr0 + tid, N) * N;
        } else if (tid < 120) {
            colmapT[tid - 43] = refl(gc0 + tid - 43, N);
        } else if (tid < 154) {
            const int i = tid - 120;
            const int h = refl(oy0 - 2 + i, N);
            shi[i] = min(max(h - gr0, 0), 42);
            int a, b, c; float x, y, z;
            if (h & 1) { a = refl(h - 1, N) >> 1; b = refl(h + 1, N) >> 1; c = a;
                         x = 0.5f; y = 0.5f; z = 0.f; }
            else       { a = refl(h - 2, N) >> 1; b = h >> 1; c = refl(h + 2, N) >> 1;
                         x = 0.125f; y = 0.75f; z = 0.125f; }
            riT[i][0] = min(max(a - R0, 0), 19);
            riT[i][1] = min(max(b - R0, 0), 19);
            riT[i][2] = min(max(c - R0, 0), 19);
            rwT[i][0] = x; rwT[i][1] = y; rwT[i][2] = z;
        } else if (tid < 220) {
            const int j = tid - 154;
            const int w = refl(ox0 - 2 + j, N);
            swj[j] = min(max(w - gc0, 0), 76);
            int a, b, c; float x, y, z;
            if (w & 1) { a = refl(w - 1, N) >> 1; b = refl(w + 1, N) >> 1; c = a;
                         x = 0.5f; y = 0.5f; z = 0.f; }
            else       { a = refl(w - 2, N) >> 1; b = w >> 1; c = refl(w + 2, N) >> 1;
                         x = 0.125f; y = 0.75f; z = 0.125f; }
            ciT[j][0] = min(max(a - C0, 0), 36);
            ciT[j][1] = min(max(b - C0, 0), 36);
            ciT[j][2] = min(max(c - C0, 0), 36);
            cwT[j][0] = x; cwT[j][1] = y; cwT[j][2] = z;
        }
        __syncthreads();
    }

    for (int img = 0; img < 2; img++) {
        const float* cur = img ? cur1 : cur0;
        float* s_t = &s_df[img][0][0];   // phase-B scratch (pitch 80), dead until D

        // ---- A: load cur tile into smem ----
        if (interior) {
#pragma unroll
            for (int r = ty; r < 43; r += 16) {
                const float* rp = cur + (gr0 + r) * N + gc0;
#pragma unroll
                for (int c = 2 * tx; c < 78; c += 64)
                    *(float2*)&s_cur[r][c] = *(const float2*)(rp + c);
            }
        } else {
#pragma unroll
            for (int r = ty; r < 43; r += 16) {
                const int ro = rowoffT[r];
#pragma unroll
                for (int c = tx; c < 77; c += 32)
                    s_cur[r][c] = __ldg(&cur[ro + colmapT[c]]);
            }
        }
        __syncthreads();

        // ---- B1: vertical 5-tap [1,4,6,4,1] at down rows (float4) ----
#pragma unroll
        for (int r = ty; r < 20; r += 16) {
            if (tx < 20) {
                const int rs = 2 * r, c4 = 4 * tx;
                float4 a0 = *(const float4*)&s_cur[rs + 0][c4];
                float4 a1 = *(const float4*)&s_cur[rs + 1][c4];
                float4 a2 = *(const float4*)&s_cur[rs + 2][c4];
                float4 a3 = *(const float4*)&s_cur[rs + 3][c4];
                float4 a4 = *(const float4*)&s_cur[rs + 4][c4];
                float4 o;
                o.x = a0.x + 4.f * (a1.x + a3.x) + 6.f * a2.x + a4.x;
                o.y = a0.y + 4.f * (a1.y + a3.y) + 6.f * a2.y + a4.y;
                o.z = a0.z + 4.f * (a1.z + a3.z) + 6.f * a2.z + a4.z;
                o.w = a0.w + 4.f * (a1.w + a3.w) + 6.f * a2.w + a4.w;
                *(float4*)&s_t[r * 80 + c4] = o;
            }
        }
        __syncthreads();

        // ---- B2: horizontal 5-tap at stride-2 -> down window (2 outputs/thread) ----
#pragma unroll
        for (int r = ty; r < 20; r += 16) {
            if (tx < 19) {
                const float* t = &s_t[r * 80 + 4 * tx];
                float4 q0 = *(const float4*)t;
                float4 q1 = *(const float4*)(t + 4);
                float o0 = (q0.x + 4.f * q0.y + 6.f * q0.z + 4.f * q0.w + q1.x)
                         * (1.0f / 256.0f);
                float o1 = (q0.z + 4.f * q0.w + 6.f * q1.x + 4.f * q1.y + q1.z)
                         * (1.0f / 256.0f);
                *(float2*)&s_dw[r][2 * tx] = make_float2(o0, o1);
            }
        }
        __syncthreads();

        // ---- B3: write block-owned 16x32 down piece for the next level ----
        if constexpr (LVL < 2) {
            const int bi = blockIdx.y, bj = blockIdx.x;
            if (bi < (N2 >> 4) && bj < (N2 >> 5)) {
                float* dn = img ? dn1 : dn0;
                dn[(size_t)((bi << 4) + ty) * N2 + (bj << 5) + tx] =
                    s_dw[(bi << 4) - R0 + ty][(bj << 5) - C0 + tx];
            }
        }

        // ---- C: horizontal up pass over down rows ----
        if (interior) {
#pragma unroll
            for (int r = ty; r < 20; r += 16) {
                for (int q = tx; q < 33; q += 32) {
                    float a = s_dw[r][q], b = s_dw[r][q + 1], c = s_dw[r][q + 2];
                    float e = 0.125f * a + 0.75f * b + 0.125f * c;  // even j=2q
                    float o = 0.5f * (b + c);                        // odd j=2q+1
                    *(float2*)&s_h[r][2 * q] = make_float2(e, o);
                }
            }
        } else {
#pragma unroll
            for (int r = ty; r < 20; r += 16) {
#pragma unroll
                for (int j = tx; j < 66; j += 32)
                    s_h[r][j] = cwT[j][0] * s_dw[r][ciT[j][0]]
                              + cwT[j][1] * s_dw[r][ciT[j][1]]
                              + cwT[j][2] * s_dw[r][ciT[j][2]];
            }
        }
        __syncthreads();

        // ---- D: vertical up pass + diff (cur from smem) ----
        if (interior) {
#pragma unroll
            for (int i = ty; i < 34; i += 16) {
                int a, b, c; float w0, w1, w2;
                if (i & 1) { a = (i + 1) >> 1; b = (i + 3) >> 1; c = a;
                             w0 = 0.5f; w1 = 0.5f; w2 = 0.f; }
                else       { a = i >> 1; b = a + 1; c = a + 2;
                             w0 = 0.125f; w1 = 0.75f; w2 = 0.125f; }
                for (int q = tx; q < 33; q += 32) {
                    const int j = 2 * q;
                    float2 ha = *(const float2*)&s_h[a][j];
                    float2 hb = *(const float2*)&s_h[b][j];
                    float2 hc = *(const float2*)&s_h[c][j];
                    float2 cu = *(const float2*)&s_cur[i + 4][j + 4];
                    float2 o;
                    o.x = cu.x - (w0 * ha.x + w1 * hb.x + w2 * hc.x);
                    o.y = cu.y - (w0 * ha.y + w1 * hb.y + w2 * hc.y);
                    *(float2*)&s_df[img][i][j] = o;
                }
            }
        } else {
#pragma unroll
            for (int i = ty; i < 34; i += 16) {
                const float w0 = rwT[i][0], w1 = rwT[i][1], w2 = rwT[i][2];
                const int a = riT[i][0], b = riT[i][1], cix = riT[i][2];
                const int hs = shi[i];
#pragma unroll
                for (int j = tx; j < 66; j += 32)
                    s_df[img][i][j] = s_cur[hs][swj[j]]
                        - (w0 * s_h[a][j] + w1 * s_h[b][j] + w2 * s_h[cix][j]);
            }
        }
        __syncthreads();
    }

    // ---- E: sobel |GX|+|GY| per image, |m0-m1|; each thread owns a 1x4 strip ----
    // incremental accumulation keeps the live set small (t[6], v[6], u[6], m0[4])
    float val = 0.f;
    {
        const int row = tid >> 4;        // 0..31
        const int c0  = (tid & 15) << 2; // 0,4,..,60
        const bool rowok = (oy0 + row) < N + 2;
        float m0[4];
#pragma unroll
        for (int im = 0; im < 2; im++) {
            float t[6], v[6], u[6];
            // row 0
            {
                const float4 a = *(const float4*)&s_df[im][row][c0];
                const float2 b = *(const float2*)&s_df[im][row][c0 + 4];
                t[0] = a.x; t[1] = a.y; t[2] = a.z; t[3] = a.w; t[4] = b.x; t[5] = b.y;
            }
#pragma unroll
            for (int j = 0; j < 6; j++) { v[j] = 2.f * t[j]; u[j] = 2.f * t[j]; }
            // row 1
            {
                const float4 a = *(const float4*)&s_df[im][row + 1][c0];
                const float2 b = *(const float2*)&s_df[im][row + 1][c0 + 4];
                t[0] = a.x; t[1] = a.y; t[2] = a.z; t[3] = a.w; t[4] = b.x; t[5] = b.y;
            }
#pragma unroll
            for (int j = 0; j < 6; j++) v[j] += 4.f * t[j];
            // row 2
            {
                const float4 a = *(const float4*)&s_df[im][row + 2][c0];
                const float2 b = *(const float2*)&s_df[im][row + 2][c0 + 4];
                t[0] = a.x; t[1] = a.y; t[2] = a.z; t[3] = a.w; t[4] = b.x; t[5] = b.y;
            }
#pragma unroll
            for (int j = 0; j < 6; j++) { v[j] += 2.f * t[j]; u[j] -= 2.f * t[j]; }
#pragma unroll
            for (int k = 0; k < 4; k++) {
                float gx = v[k] - v[k + 2];
                float gy = u[k] + 2.f * u[k + 1] + u[k + 2];
                float m = fabsf(gx) + fabsf(gy);
                if (im == 0) m0[k] = m;
                else if (rowok && (ox0 + c0 + k) < N + 2)
                    val += fabsf(m0[k] - m);
            }
        }
    }

    // ---- block reduction -> one double atomic per block ----
#pragma unroll
    for (int off = 16; off > 0; off >>= 1)
        val += __shfl_down_sync(0xffffffffu, val, off);
    if ((tid & 31) == 0) warpsum[tid >> 5] = val;
    __syncthreads();
    if (tid < 16) {
        float v = warpsum[tid];
#pragma unroll
        for (int off = 8; off > 0; off >>= 1)
            v += __shfl_down_sync(0xffffu, v, off);
        if (tid == 0) atomicAdd(&g_acc[LVL], (double)v);
    }
}

__global__ void finalize_kernel(float* __restrict__ out) {
    double l = g_acc[0] / ((double)PLANES * 514.0 * 514.0)
             + g_acc[1] / ((double)PLANES * 258.0 * 258.0)
             + g_acc[2] / ((double)PLANES * 130.0 * 130.0);
    out[0] = (float)l;
}

// -------------------------------------------------------------------------------
extern "C" void kernel_launch(void* const* d_in, const int* in_sizes, int n_in,
                              void* d_out, int out_size) {
    const float* inp = (const float*)d_in[0];
    const float* tgt = (const float*)d_in[1];
    // d_in[2] (gauss_kernel) is a fixed constant — baked into the kernels.
    float* out = (float*)d_out;

    zero_acc_kernel<<<1, 32>>>();

    lap_kernel<0><<<dim3(9, 17, PLANES), dim3(32, 16)>>>(inp, tgt);  // N=512
    lap_kernel<1><<<dim3(5, 9, PLANES),  dim3(32, 16)>>>(inp, tgt);  // N=256
    lap_kernel<2><<<dim3(3, 5, PLANES),  dim3(32, 16)>>>(inp, tgt);  // N=128

    finalize_kernel<<<1, 1>>>(out);
}

// round 12
// speedup vs baseline: 1.5379x; 1.2097x over previous
#include <cuda_runtime.h>

#define PLANES 48  // B*C = 16*3

// ---------------- static device scratch (no allocations allowed) ----------------
__device__ float g_d1[2][PLANES * 256 * 256];  // level-0 downs == level-1 currents
__device__ float g_d2[2][PLANES * 128 * 128];  // level-1 downs == level-2 currents
__device__ double g_acc[3];                    // per-level |.| sums

// reflect index (numpy 'reflect', pad<=2): -1->1, -2->2, n->n-2, n+1->n-3
__device__ __forceinline__ int refl(int p, int n) {
    p = (p < 0) ? -p : p;
    return (p >= n) ? (2 * n - 2 - p) : p;
}

__global__ void zero_acc_kernel() {
    if (threadIdx.x < 3) g_acc[threadIdx.x] = 0.0;
}

// -------------------------------------------------------------------------------
// lap_kernel<LVL>: fused down+up+diff+sobel+reduce, one kernel per level.
// block (32,16)=512 threads. Grid tiles N exactly: (N/64, N/32, 48).
// Each block computes a 36x68 diff tile; normal blocks emit 32x64 loss outputs,
// the globally-last row/col blocks emit 34/66 (the +2 overflow lives in the halo).
// Interior blocks take a fully-linear vectorized path.
// -------------------------------------------------------------------------------
template <int LVL>
__global__ __launch_bounds__(512, 4) void lap_kernel(const float* __restrict__ extA,
                                                     const float* __restrict__ extB) {
    constexpr int N  = (LVL == 0) ? 512 : (LVL == 1) ? 256 : 128;
    constexpr int N2 = N >> 1;

    const int p = blockIdx.z;
    const float *cur0, *cur1;
    float *dn0 = nullptr, *dn1 = nullptr;
    if constexpr (LVL == 0) {
        cur0 = extA + (size_t)p * N * N;     cur1 = extB + (size_t)p * N * N;
        dn0 = g_d1[0] + (size_t)p * N2 * N2; dn1 = g_d1[1] + (size_t)p * N2 * N2;
    } else if constexpr (LVL == 1) {
        cur0 = g_d1[0] + (size_t)p * N * N;  cur1 = g_d1[1] + (size_t)p * N * N;
        dn0 = g_d2[0] + (size_t)p * N2 * N2; dn1 = g_d2[1] + (size_t)p * N2 * N2;
    } else {
        cur0 = g_d2[0] + (size_t)p * N * N;  cur1 = g_d2[1] + (size_t)p * N * N;
    }

    __shared__ __align__(16) float s_cur[43][80];    // reflected cur tile
    __shared__ __align__(16) float s_dw[20][40];     // down window
    __shared__ __align__(16) float s_h[20][68];      // horizontally upsampled rows
    __shared__ __align__(16) float s_df[2][36][72];  // diff tiles (also phase-B scratch)
    __shared__ int rowoffT[43], colmapT[77];
    __shared__ int shi[36], riT[36][3];
    __shared__ float rwT[36][3];
    __shared__ int swj[68], ciT[68][3];
    __shared__ float cwT[68][3];
    __shared__ float warpsum[16];

    const int tx = threadIdx.x, ty = threadIdx.y;
    const int tid = ty * 32 + tx;
    const int oy0 = blockIdx.y * 32, ox0 = blockIdx.x * 64;
    const int R0 = max(0, (oy0 - 4) >> 1);
    const int C0 = max(0, (ox0 - 4) >> 1);
    const int gr0 = 2 * R0 - 2;   // cur tile global row 0
    const int gc0 = 2 * C0 - 2;   // cur tile global col 0

    const bool interior = (gr0 >= 0) && (gr0 + 42 <= N - 1)
                       && (gc0 >= 0) && (gc0 + 77 <= N - 1);

    // ---- boundary-only tables ----
    if (!interior) {
        if (tid < 43) {
            rowoffT[tid] = refl(gr0 + tid, N) * N;
        } else if (tid < 120) {
            colmapT[tid - 43] = refl(gc0 + tid - 43, N);
        } else if (tid < 156) {
            const int i = tid - 120;
            const int h = refl(oy0 - 2 + i, N);
            shi[i] = min(max(h - gr0, 0), 42);
            int a, b, c; float x, y, z;
            if (h & 1) { a = refl(h - 1, N) >> 1; b = refl(h + 1, N) >> 1; c = a;
                         x = 0.5f; y = 0.5f; z = 0.f; }
            else       { a = refl(h - 2, N) >> 1; b = h >> 1; c = refl(h + 2, N) >> 1;
                         x = 0.125f; y = 0.75f; z = 0.125f; }
            riT[i][0] = min(max(a - R0, 0), 19);
            riT[i][1] = min(max(b - R0, 0), 19);
            riT[i][2] = min(max(c - R0, 0), 19);
            rwT[i][0] = x; rwT[i][1] = y; rwT[i][2] = z;
        } else if (tid < 224) {
            const int j = tid - 156;
            const int w = refl(ox0 - 2 + j, N);
            swj[j] = min(max(w - gc0, 0), 76);
            int a, b, c; float x, y, z;
            if (w & 1) { a = refl(w - 1, N) >> 1; b = refl(w + 1, N) >> 1; c = a;
                         x = 0.5f; y = 0.5f; z = 0.f; }
            else       { a = refl(w - 2, N) >> 1; b = w >> 1; c = refl(w + 2, N) >> 1;
                         x = 0.125f; y = 0.75f; z = 0.125f; }
            ciT[j][0] = min(max(a - C0, 0), 36);
            ciT[j][1] = min(max(b - C0, 0), 36);
            ciT[j][2] = min(max(c - C0, 0), 36);
            cwT[j][0] = x; cwT[j][1] = y; cwT[j][2] = z;
        }
        __syncthreads();
    }

    for (int img = 0; img < 2; img++) {
        const float* cur = img ? cur1 : cur0;
        float* s_t = &s_df[img][0][0];   // phase-B scratch (pitch 80), dead until D

        // ---- A: load cur tile into smem ----
        if (interior) {
#pragma unroll
            for (int r = ty; r < 43; r += 16) {
                const float* rp = cur + (gr0 + r) * N + gc0;
#pragma unroll
                for (int c = 2 * tx; c < 78; c += 64)
                    *(float2*)&s_cur[r][c] = *(const float2*)(rp + c);
            }
        } else {
#pragma unroll
            for (int r = ty; r < 43; r += 16) {
                const int ro = rowoffT[r];
#pragma unroll
                for (int c = tx; c < 77; c += 32)
                    s_cur[r][c] = __ldg(&cur[ro + colmapT[c]]);
            }
        }
        __syncthreads();

        // ---- B1: vertical 5-tap [1,4,6,4,1] at down rows (float4) ----
#pragma unroll
        for (int r = ty; r < 20; r += 16) {
            if (tx < 20) {
                const int rs = 2 * r, c4 = 4 * tx;
                float4 a0 = *(const float4*)&s_cur[rs + 0][c4];
                float4 a1 = *(const float4*)&s_cur[rs + 1][c4];
                float4 a2 = *(const float4*)&s_cur[rs + 2][c4];
                float4 a3 = *(const float4*)&s_cur[rs + 3][c4];
                float4 a4 = *(const float4*)&s_cur[rs + 4][c4];
                float4 o;
                o.x = a0.x + 4.f * (a1.x + a3.x) + 6.f * a2.x + a4.x;
                o.y = a0.y + 4.f * (a1.y + a3.y) + 6.f * a2.y + a4.y;
                o.z = a0.z + 4.f * (a1.z + a3.z) + 6.f * a2.z + a4.z;
                o.w = a0.w + 4.f * (a1.w + a3.w) + 6.f * a2.w + a4.w;
                *(float4*)&s_t[r * 80 + c4] = o;
            }
        }
        __syncthreads();

        // ---- B2: horizontal 5-tap at stride-2 -> down window (2 outputs/thread) ----
#pragma unroll
        for (int r = ty; r < 20; r += 16) {
            if (tx < 19) {
                const float* t = &s_t[r * 80 + 4 * tx];
                float4 q0 = *(const float4*)t;
                float4 q1 = *(const float4*)(t + 4);
                float o0 = (q0.x + 4.f * q0.y + 6.f * q0.z + 4.f * q0.w + q1.x)
                         * (1.0f / 256.0f);
                float o1 = (q0.z + 4.f * q0.w + 6.f * q1.x + 4.f * q1.y + q1.z)
                         * (1.0f / 256.0f);
                *(float2*)&s_dw[r][2 * tx] = make_float2(o0, o1);
            }
        }
        __syncthreads();

        // ---- B3: write block-owned 16x32 down piece (grid covers plane exactly) ----
        if constexpr (LVL < 2) {
            const int bi = blockIdx.y, bj = blockIdx.x;
            float* dn = img ? dn1 : dn0;
            dn[(size_t)((bi << 4) + ty) * N2 + (bj << 5) + tx] =
                s_dw[(bi << 4) - R0 + ty][(bj << 5) - C0 + tx];
        }

        // ---- C: horizontal up pass over down rows (68 cols) ----
        if (interior) {
#pragma unroll
            for (int r = ty; r < 20; r += 16) {
                for (int q = tx; q < 34; q += 32) {
                    float a = s_dw[r][q], b = s_dw[r][q + 1], c = s_dw[r][q + 2];
                    float e = 0.125f * a + 0.75f * b + 0.125f * c;  // even j=2q
                    float o = 0.5f * (b + c);                        // odd j=2q+1
                    *(float2*)&s_h[r][2 * q] = make_float2(e, o);
                }
            }
        } else {
#pragma unroll
            for (int r = ty; r < 20; r += 16) {
#pragma unroll
                for (int j = tx; j < 68; j += 32)
                    s_h[r][j] = cwT[j][0] * s_dw[r][ciT[j][0]]
                              + cwT[j][1] * s_dw[r][ciT[j][1]]
                              + cwT[j][2] * s_dw[r][ciT[j][2]];
            }
        }
        __syncthreads();

        // ---- D: vertical up pass + diff (36 rows x 68 cols) ----
        if (interior) {
#pragma unroll
            for (int i = ty; i < 36; i += 16) {
                int a, b, c; float w0, w1, w2;
                if (i & 1) { a = (i + 1) >> 1; b = (i + 3) >> 1; c = a;
                             w0 = 0.5f; w1 = 0.5f; w2 = 0.f; }
                else       { a = i >> 1; b = a + 1; c = a + 2;
                             w0 = 0.125f; w1 = 0.75f; w2 = 0.125f; }
                for (int q = tx; q < 34; q += 32) {
                    const int j = 2 * q;
                    float2 ha = *(const float2*)&s_h[a][j];
                    float2 hb = *(const float2*)&s_h[b][j];
                    float2 hc = *(const float2*)&s_h[c][j];
                    float2 cu = *(const float2*)&s_cur[i + 4][j + 4];
                    float2 o;
                    o.x = cu.x - (w0 * ha.x + w1 * hb.x + w2 * hc.x);
                    o.y = cu.y - (w0 * ha.y + w1 * hb.y + w2 * hc.y);
                    *(float2*)&s_df[img][i][j] = o;
                }
            }
        } else {
#pragma unroll
            for (int i = ty; i < 36; i += 16) {
                const float w0 = rwT[i][0], w1 = rwT[i][1], w2 = rwT[i][2];
                const int a = riT[i][0], b = riT[i][1], cix = riT[i][2];
                const int hs = shi[i];
#pragma unroll
                for (int j = tx; j < 68; j += 32)
                    s_df[img][i][j] = s_cur[hs][swj[j]]
                        - (w0 * s_h[a][j] + w1 * s_h[b][j] + w2 * s_h[cix][j]);
            }
        }
        __syncthreads();
    }

    // ---- E: sobel |GX|+|GY| per image, |m0-m1|; flat item loop over 36x17 strips ----
    float val = 0.f;
    {
        const int rows_out = (blockIdx.y == gridDim.y - 1) ? 34 : 32;
        const int cols_out = (blockIdx.x == gridDim.x - 1) ? 66 : 64;
        for (int item = tid; item < 36 * 17; item += 512) {
            const int row = item / 17;
            const int c0 = (item - row * 17) * 4;
            if (row >= rows_out) continue;
            float m0[4];
#pragma unroll
            for (int im = 0; im < 2; im++) {
                float t[6], v[6], u[6];
                {
                    const float4 a = *(const float4*)&s_df[im][row][c0];
                    const float2 b = *(const float2*)&s_df[im][row][c0 + 4];
                    t[0] = a.x; t[1] = a.y; t[2] = a.z; t[3] = a.w; t[4] = b.x; t[5] = b.y;
                }
#pragma unroll
                for (int j = 0; j < 6; j++) { v[j] = 2.f * t[j]; u[j] = 2.f * t[j]; }
                {
                    const float4 a = *(const float4*)&s_df[im][row + 1][c0];
                    const float2 b = *(const float2*)&s_df[im][row + 1][c0 + 4];
                    t[0] = a.x; t[1] = a.y; t[2] = a.z; t[3] = a.w; t[4] = b.x; t[5] = b.y;
                }
#pragma unroll
                for (int j = 0; j < 6; j++) v[j] += 4.f * t[j];
                {
                    const float4 a = *(const float4*)&s_df[im][row + 2][c0];
                    const float2 b = *(const float2*)&s_df[im][row + 2][c0 + 4];
                    t[0] = a.x; t[1] = a.y; t[2] = a.z; t[3] = a.w; t[4] = b.x; t[5] = b.y;
                }
#pragma unroll
                for (int j = 0; j < 6; j++) { v[j] += 2.f * t[j]; u[j] -= 2.f * t[j]; }
#pragma unroll
                for (int k = 0; k < 4; k++) {
                    float gx = v[k] - v[k + 2];
                    float gy = u[k] + 2.f * u[k + 1] + u[k + 2];
                    float m = fabsf(gx) + fabsf(gy);
                    if (im == 0) m0[k] = m;
                    else if (c0 + k < cols_out) val += fabsf(m0[k] - m);
                }
            }
        }
    }

    // ---- block reduction -> one double atomic per block ----
#pragma unroll
    for (int off = 16; off > 0; off >>= 1)
        val += __shfl_down_sync(0xffffffffu, val, off);
    if ((tid & 31) == 0) warpsum[tid >> 5] = val;
    __syncthreads();
    if (tid < 16) {
        float v = warpsum[tid];
#pragma unroll
        for (int off = 8; off > 0; off >>= 1)
            v += __shfl_down_sync(0xffffu, v, off);
        if (tid == 0) atomicAdd(&g_acc[LVL], (double)v);
    }
}

__global__ void finalize_kernel(float* __restrict__ out) {
    double l = g_acc[0] / ((double)PLANES * 514.0 * 514.0)
             + g_acc[1] / ((double)PLANES * 258.0 * 258.0)
             + g_acc[2] / ((double)PLANES * 130.0 * 130.0);
    out[0] = (float)l;
}

// -------------------------------------------------------------------------------
extern "C" void kernel_launch(void* const* d_in, const int* in_sizes, int n_in,
                              void* d_out, int out_size) {
    const float* inp = (const float*)d_in[0];
    const float* tgt = (const float*)d_in[1];
    // d_in[2] (gauss_kernel) is a fixed constant — baked into the kernels.
    float* out = (float*)d_out;

    zero_acc_kernel<<<1, 32>>>();

    lap_kernel<0><<<dim3(8, 16, PLANES), dim3(32, 16)>>>(inp, tgt);  // N=512
    lap_kernel<1><<<dim3(4, 8, PLANES),  dim3(32, 16)>>>(inp, tgt);  // N=256
    lap_kernel<2><<<dim3(2, 4, PLANES),  dim3(32, 16)>>>(inp, tgt);  // N=128

    finalize_kernel<<<1, 1>>>(out);
}

// round 13
// speedup vs baseline: 1.6911x; 1.0996x over previous
#include <cuda_runtime.h>

#define PLANES 48  // B*C = 16*3

// ---------------- static device scratch (no allocations allowed) ----------------
__device__ float g_d1[2][PLANES * 256 * 256];  // level-0 downs == level-1 currents
__device__ float g_d2[2][PLANES * 128 * 128];  // level-1 downs == level-2 currents
__device__ double g_acc[3];                    // per-level |.| sums

// reflect index (numpy 'reflect'): valid for |p| well under n
__device__ __forceinline__ int refl(int p, int n) {
    p = (p < 0) ? -p : p;
    return (p >= n) ? (2 * n - 2 - p) : p;
}

__global__ void zero_acc_kernel() {
    if (threadIdx.x < 3) g_acc[threadIdx.x] = 0.0;
}

// -------------------------------------------------------------------------------
// lap_kernel<LVL>: fused down+up+diff+sobel+reduce in PADDED coordinates.
// block (32,16)=512 threads. Grid tiles N exactly: (N/64, N/32, 48).
// s_cur holds the tile at padded origin (oy0-6, ox0-6) (border duplicates), so
// phases B2/C/D/E are one vectorized linear path for ALL blocks. Down-window
// halo rows are folded in B1 (free); halo columns are fixed by in-smem copies.
// -------------------------------------------------------------------------------
template <int LVL>
__global__ __launch_bounds__(512, 4) void lap_kernel(const float* __restrict__ extA,
                                                     const float* __restrict__ extB) {
    constexpr int N  = (LVL == 0) ? 512 : (LVL == 1) ? 256 : 128;
    constexpr int N2 = N >> 1;

    const int p = blockIdx.z;
    const float *cur0, *cur1;
    float *dn0 = nullptr, *dn1 = nullptr;
    if constexpr (LVL == 0) {
        cur0 = extA + (size_t)p * N * N;     cur1 = extB + (size_t)p * N * N;
        dn0 = g_d1[0] + (size_t)p * N2 * N2; dn1 = g_d1[1] + (size_t)p * N2 * N2;
    } else if constexpr (LVL == 1) {
        cur0 = g_d1[0] + (size_t)p * N * N;  cur1 = g_d1[1] + (size_t)p * N * N;
        dn0 = g_d2[0] + (size_t)p * N2 * N2; dn1 = g_d2[1] + (size_t)p * N2 * N2;
    } else {
        cur0 = g_d2[0] + (size_t)p * N * N;  cur1 = g_d2[1] + (size_t)p * N * N;
    }

    __shared__ __align__(16) float s_cur[43][80];    // padded cur tile
    __shared__ __align__(16) float s_dw[20][40];     // down window (padded coarse)
    __shared__ __align__(16) float s_h[20][68];      // horizontally upsampled rows
    __shared__ __align__(16) float s_df[2][36][72];  // diff tiles (also phase-B scratch)
    __shared__ int rowoffT[43], colmapT[77];
    __shared__ float warpsum[16];

    const int tx = threadIdx.x, ty = threadIdx.y;
    const int tid = ty * 32 + tx;
    const int oy0 = blockIdx.y * 32, ox0 = blockIdx.x * 64;
    const int crmin = (oy0 >> 1) - 2;   // padded coarse row origin of s_dw
    const int gr0p = oy0 - 6;           // padded fine row origin of s_cur
    const int gc0p = ox0 - 6;           // padded fine col origin of s_cur

    const bool interiorA = (gr0p >= 0) && (gr0p + 42 <= N - 1)
                        && (gc0p >= 0) && (gc0p + 76 <= N - 1);
    const bool ecol_lo = (blockIdx.x == 0);
    const bool ecol_hi = (blockIdx.x == gridDim.x - 1);

    // ---- phase-A address tables (boundary blocks only) ----
    if (!interiorA) {
        if (tid < 43) rowoffT[tid] = refl(gr0p + tid, N) * N;
        else if (tid < 120) colmapT[tid - 43] = refl(gc0p + tid - 43, N);
        __syncthreads();
    }

    for (int img = 0; img < 2; img++) {
        const float* cur = img ? cur1 : cur0;
        float* s_t = &s_df[img][0][0];   // phase-B scratch (pitch 80), dead until D

        // ---- A: load padded cur tile 43x77 into smem ----
        if (interiorA) {
#pragma unroll
            for (int r = ty; r < 43; r += 16) {
                const float* rp = cur + (gr0p + r) * N + gc0p;
#pragma unroll
                for (int c = 2 * tx; c < 77; c += 64)
                    *(float2*)&s_cur[r][c] = *(const float2*)(rp + c);
            }
        } else {
#pragma unroll
            for (int r = ty; r < 43; r += 16) {
                const int ro = rowoffT[r];
#pragma unroll
                for (int c = tx; c < 77; c += 32)
                    s_cur[r][c] = __ldg(&cur[ro + colmapT[c]]);
            }
        }
        __syncthreads();

        // ---- B1: vertical 5-tap at folded coarse rows (float4) ----
#pragma unroll
        for (int r = ty; r < 20; r += 16) {
            if (tx < 20) {
                int cr = crmin + r;
                int src = (cr < 0) ? -cr : ((cr >= N2) ? 2 * N2 - 1 - cr : cr);
                const int fb = 2 * src + 4 - oy0;   // s_cur row of fine 2*src-2
                const int c4 = 4 * tx;
                float4 a0 = *(const float4*)&s_cur[fb + 0][c4];
                float4 a1 = *(const float4*)&s_cur[fb + 1][c4];
                float4 a2 = *(const float4*)&s_cur[fb + 2][c4];
                float4 a3 = *(const float4*)&s_cur[fb + 3][c4];
                float4 a4 = *(const float4*)&s_cur[fb + 4][c4];
                float4 o;
                o.x = a0.x + 4.f * (a1.x + a3.x) + 6.f * a2.x + a4.x;
                o.y = a0.y + 4.f * (a1.y + a3.y) + 6.f * a2.y + a4.y;
                o.z = a0.z + 4.f * (a1.z + a3.z) + 6.f * a2.z + a4.z;
                o.w = a0.w + 4.f * (a1.w + a3.w) + 6.f * a2.w + a4.w;
                *(float4*)&s_t[r * 80 + c4] = o;
            }
        }
        __syncthreads();

        // ---- B2: horizontal 5-tap at stride-2 -> down window 20x36 (linear) ----
#pragma unroll
        for (int r = ty; r < 20; r += 16) {
            if (tx < 18) {
                const float* t = &s_t[r * 80 + 4 * tx];
                float4 q0 = *(const float4*)t;
                float4 q1 = *(const float4*)(t + 4);
                float o0 = (q0.x + 4.f * q0.y + 6.f * q0.z + 4.f * q0.w + q1.x)
                         * (1.0f / 256.0f);
                float o1 = (q0.z + 4.f * q0.w + 6.f * q1.x + 4.f * q1.y + q1.z)
                         * (1.0f / 256.0f);
                *(float2*)&s_dw[r][2 * tx] = make_float2(o0, o1);
            }
        }
        __syncthreads();

        // ---- B2b: fold halo COLUMNS (pure smem copies; edge-col blocks only) ----
        if (ecol_lo || ecol_hi) {
            if (tid < 20) {
                if (ecol_lo) {   // cc=-2 -> src 2 (idx 4);  cc=-1 -> src 1 (idx 3)
                    s_dw[tid][0] = s_dw[tid][4];
                    s_dw[tid][1] = s_dw[tid][3];
                }
                if (ecol_hi) {   // cc=N2 -> N2-1 (idx 33);  cc=N2+1 -> N2-2 (idx 32)
                    s_dw[tid][34] = s_dw[tid][33];
                    s_dw[tid][35] = s_dw[tid][32];
                }
            }
            __syncthreads();
        }

        // ---- B3: write block-owned 16x32 down piece (fixed offsets) ----
        if constexpr (LVL < 2) {
            float* dn = img ? dn1 : dn0;
            dn[(size_t)((blockIdx.y << 4) + ty) * N2 + (blockIdx.x << 5) + tx] =
                s_dw[ty + 2][tx + 2];
        }

        // ---- C: horizontal up pass over down rows (linear, all blocks) ----
#pragma unroll
        for (int r = ty; r < 20; r += 16) {
            for (int q = tx; q < 34; q += 32) {
                float a = s_dw[r][q], b = s_dw[r][q + 1], c = s_dw[r][q + 2];
                float e = 0.125f * a + 0.75f * b + 0.125f * c;  // even j=2q
                float o = 0.5f * (b + c);                        // odd j=2q+1
                *(float2*)&s_h[r][2 * q] = make_float2(e, o);
            }
        }
        __syncthreads();

        // ---- D: vertical up pass + diff (linear, all blocks) ----
#pragma unroll
        for (int i = ty; i < 36; i += 16) {
            int a, b, c; float w0, w1, w2;
            if (i & 1) { a = (i + 1) >> 1; b = (i + 3) >> 1; c = a;
                         w0 = 0.5f; w1 = 0.5f; w2 = 0.f; }
            else       { a = i >> 1; b = a + 1; c = a + 2;
                         w0 = 0.125f; w1 = 0.75f; w2 = 0.125f; }
            for (int q = tx; q < 34; q += 32) {
                const int j = 2 * q;
                float2 ha = *(const float2*)&s_h[a][j];
                float2 hb = *(const float2*)&s_h[b][j];
                float2 hc = *(const float2*)&s_h[c][j];
                float2 cu = *(const float2*)&s_cur[i + 4][j + 4];
                float2 o;
                o.x = cu.x - (w0 * ha.x + w1 * hb.x + w2 * hc.x);
                o.y = cu.y - (w0 * ha.y + w1 * hb.y + w2 * hc.y);
                *(float2*)&s_df[img][i][j] = o;
            }
        }
        __syncthreads();
    }

    // ---- E: sobel |GX|+|GY| per image, |m0-m1|; flat item loop over 36x17 strips ----
    float val = 0.f;
    {
        const int rows_out = (blockIdx.y == gridDim.y - 1) ? 34 : 32;
        const int cols_out = ecol_hi ? 66 : 64;
        for (int item = tid; item < 36 * 17; item += 512) {
            const int row = item / 17;
            const int c0 = (item - row * 17) * 4;
            if (row >= rows_out) continue;
            float m0[4];
#pragma unroll
            for (int im = 0; im < 2; im++) {
                float t[6], v[6], u[6];
                {
                    const float4 a = *(const float4*)&s_df[im][row][c0];
                    const float2 b = *(const float2*)&s_df[im][row][c0 + 4];
                    t[0] = a.x; t[1] = a.y; t[2] = a.z; t[3] = a.w; t[4] = b.x; t[5] = b.y;
                }
#pragma unroll
                for (int j = 0; j < 6; j++) { v[j] = 2.f * t[j]; u[j] = 2.f * t[j]; }
                {
                    const float4 a = *(const float4*)&s_df[im][row + 1][c0];
                    const float2 b = *(const float2*)&s_df[im][row + 1][c0 + 4];
                    t[0] = a.x; t[1] = a.y; t[2] = a.z; t[3] = a.w; t[4] = b.x; t[5] = b.y;
                }
#pragma unroll
                for (int j = 0; j < 6; j++) v[j] += 4.f * t[j];
                {
                    const float4 a = *(const float4*)&s_df[im][row + 2][c0];
                    const float2 b = *(const float2*)&s_df[im][row + 2][c0 + 4];
                    t[0] = a.x; t[1] = a.y; t[2] = a.z; t[3] = a.w; t[4] = b.x; t[5] = b.y;
                }
#pragma unroll
                for (int j = 0; j < 6; j++) { v[j] += 2.f * t[j]; u[j] -= 2.f * t[j]; }
#pragma unroll
                for (int k = 0; k < 4; k++) {
                    float gx = v[k] - v[k + 2];
                    float gy = u[k] + 2.f * u[k + 1] + u[k + 2];
                    float m = fabsf(gx) + fabsf(gy);
                    if (im == 0) m0[k] = m;
                    else if (c0 + k < cols_out) val += fabsf(m0[k] - m);
                }
            }
        }
    }

    // ---- block reduction -> one double atomic per block ----
#pragma unroll
    for (int off = 16; off > 0; off >>= 1)
        val += __shfl_down_sync(0xffffffffu, val, off);
    if ((tid & 31) == 0) warpsum[tid >> 5] = val;
    __syncthreads();
    if (tid < 16) {
        float v = warpsum[tid];
#pragma unroll
        for (int off = 8; off > 0; off >>= 1)
            v += __shfl_down_sync(0xffffu, v, off);
        if (tid == 0) atomicAdd(&g_acc[LVL], (double)v);
    }
}

__global__ void finalize_kernel(float* __restrict__ out) {
    double l = g_acc[0] / ((double)PLANES * 514.0 * 514.0)
             + g_acc[1] / ((double)PLANES * 258.0 * 258.0)
             + g_acc[2] / ((double)PLANES * 130.0 * 130.0);
    out[0] = (float)l;
}

// -------------------------------------------------------------------------------
extern "C" void kernel_launch(void* const* d_in, const int* in_sizes, int n_in,
                              void* d_out, int out_size) {
    const float* inp = (const float*)d_in[0];
    const float* tgt = (const float*)d_in[1];
    // d_in[2] (gauss_kernel) is a fixed constant — baked into the kernels.
    float* out = (float*)d_out;

    zero_acc_kernel<<<1, 32>>>();

    lap_kernel<0><<<dim3(8, 16, PLANES), dim3(32, 16)>>>(inp, tgt);  // N=512
    lap_kernel<1><<<dim3(4, 8, PLANES),  dim3(32, 16)>>>(inp, tgt);  // N=256
    lap_kernel<2><<<dim3(2, 4, PLANES),  dim3(32, 16)>>>(inp, tgt);  // N=128

    finalize_kernel<<<1, 1>>>(out);
}

// round 14
// speedup vs baseline: 1.6965x; 1.0032x over previous
#include <cuda_runtime.h>

#define PLANES 48  // B*C = 16*3

// ---------------- static device scratch (no allocations allowed) ----------------
__device__ float g_d1[2][PLANES * 256 * 256];  // level-0 downs == level-1 currents
__device__ float g_d2[2][PLANES * 128 * 128];  // level-1 downs == level-2 currents
__device__ double g_acc[3];                    // per-level |.| sums

// reflect index (numpy 'reflect'): valid for |p| well under n
__device__ __forceinline__ int refl(int p, int n) {
    p = (p < 0) ? -p : p;
    return (p >= n) ? (2 * n - 2 - p) : p;
}

__global__ void zero_acc_kernel() {
    if (threadIdx.x < 3) g_acc[threadIdx.x] = 0.0;
}

// -------------------------------------------------------------------------------
// lap_kernel<LVL>: fused down+up+diff+sobel+reduce in PADDED coordinates.
// block (32,16)=512 threads. Tile: 32 rows x TW cols (TW=64 for L0/L1, 32 for L2
// so the level-2 grid fills the machine). s_cur origin (oy0-6, ox0-8): the -8
// column origin makes interior phase-A loads float4-aligned. Down-window halo
// columns are written directly by the lanes that compute their source values
// (no extra barrier); halo rows folded in B1 for free.
// -------------------------------------------------------------------------------
template <int LVL>
__global__ __launch_bounds__(512, 4) void lap_kernel(const float* __restrict__ extA,
                                                     const float* __restrict__ extB) {
    constexpr int N  = (LVL == 0) ? 512 : (LVL == 1) ? 256 : 128;
    constexpr int N2 = N >> 1;
    constexpr int TW = (LVL == 2) ? 32 : 64;   // tile cols
    constexpr int CT = TW + 16;                // s_cur cols (80 / 48)
    constexpr int DWC = TW / 2 + 4;            // s_dw cols (36 / 20)
    constexpr int DWP = DWC + 4;               // s_dw pitch (40 / 24)
    constexpr int HC = TW + 4;                 // s_h cols (68 / 36)
    constexpr int DFP = TW + 8;                // s_df pitch (72 / 40)
    constexpr int NL_B1 = CT / 4;              // B1 float4 lanes (20 / 12)
    constexpr int NL_B2 = (TW + 8) / 4;        // B2 pair lanes (18 / 10)
    constexpr int STRIPS = TW / 4 + 1;         // E strips per row (17 / 9)

    const int p = blockIdx.z;
    const float *cur0, *cur1;
    float *dn0 = nullptr, *dn1 = nullptr;
    if constexpr (LVL == 0) {
        cur0 = extA + (size_t)p * N * N;     cur1 = extB + (size_t)p * N * N;
        dn0 = g_d1[0] + (size_t)p * N2 * N2; dn1 = g_d1[1] + (size_t)p * N2 * N2;
    } else if constexpr (LVL == 1) {
        cur0 = g_d1[0] + (size_t)p * N * N;  cur1 = g_d1[1] + (size_t)p * N * N;
        dn0 = g_d2[0] + (size_t)p * N2 * N2; dn1 = g_d2[1] + (size_t)p * N2 * N2;
    } else {
        cur0 = g_d2[0] + (size_t)p * N * N;  cur1 = g_d2[1] + (size_t)p * N * N;
    }

    __shared__ __align__(16) float s_cur[43][CT];     // padded cur tile
    __shared__ __align__(16) float s_dw[20][DWP];     // down window (padded coarse)
    __shared__ __align__(16) float s_h[20][HC];       // horizontally upsampled rows
    __shared__ __align__(16) float s_df[2][36][DFP];  // diff tiles (also B scratch)
    __shared__ int rowoffT[43], colmapT[CT];
    __shared__ float warpsum[16];

    const int tx = threadIdx.x, ty = threadIdx.y;
    const int tid = ty * 32 + tx;
    const int oy0 = blockIdx.y * 32, ox0 = blockIdx.x * TW;
    const int crmin = (oy0 >> 1) - 2;   // padded coarse row origin of s_dw
    const int gr0p = oy0 - 6;           // padded fine row origin of s_cur
    const int gc0p = ox0 - 8;           // padded fine col origin (16B aligned)

    const bool interiorA = (gr0p >= 0) && (gr0p + 42 <= N - 1)
                        && (gc0p >= 0) && (gc0p + CT - 1 <= N - 1);
    const bool ecol_lo = (blockIdx.x == 0);
    const bool ecol_hi = (blockIdx.x == gridDim.x - 1);

    // ---- phase-A address tables (boundary blocks only) ----
    if (!interiorA) {
        if (tid < 43) rowoffT[tid] = refl(gr0p + tid, N) * N;
        else if (tid < 43 + CT) colmapT[tid - 43] = refl(gc0p + tid - 43, N);
        __syncthreads();
    }

    for (int img = 0; img < 2; img++) {
        const float* cur = img ? cur1 : cur0;
        float* s_t = &s_df[img][0][0];   // phase-B scratch (pitch CT), dead until D

        // ---- A: load padded cur tile 43 x CT into smem ----
        if (interiorA) {
#pragma unroll
            for (int r = ty; r < 43; r += 16) {
                const float* rp = cur + (gr0p + r) * N + gc0p;
                if (tx < NL_B1)
                    *(float4*)&s_cur[r][4 * tx] = *(const float4*)(rp + 4 * tx);
            }
        } else {
#pragma unroll
            for (int r = ty; r < 43; r += 16) {
                const int ro = rowoffT[r];
#pragma unroll
                for (int c = tx; c < CT; c += 32)
                    s_cur[r][c] = __ldg(&cur[ro + colmapT[c]]);
            }
        }
        __syncthreads();

        // ---- B1: vertical 5-tap at folded coarse rows (float4, all CT cols) ----
#pragma unroll
        for (int r = ty; r < 20; r += 16) {
            if (tx < NL_B1) {
                int cr = crmin + r;
                int src = (cr < 0) ? -cr : ((cr >= N2) ? 2 * N2 - 1 - cr : cr);
                const int fb = 2 * src + 4 - oy0;   // s_cur row of fine 2*src-2
                const int c4 = 4 * tx;
                float4 a0 = *(const float4*)&s_cur[fb + 0][c4];
                float4 a1 = *(const float4*)&s_cur[fb + 1][c4];
                float4 a2 = *(const float4*)&s_cur[fb + 2][c4];
                float4 a3 = *(const float4*)&s_cur[fb + 3][c4];
                float4 a4 = *(const float4*)&s_cur[fb + 4][c4];
                float4 o;
                o.x = a0.x + 4.f * (a1.x + a3.x) + 6.f * a2.x + a4.x;
                o.y = a0.y + 4.f * (a1.y + a3.y) + 6.f * a2.y + a4.y;
                o.z = a0.z + 4.f * (a1.z + a3.z) + 6.f * a2.z + a4.z;
                o.w = a0.w + 4.f * (a1.w + a3.w) + 6.f * a2.w + a4.w;
                *(float4*)&s_t[r * CT + c4] = o;
            }
        }
        __syncthreads();

        // ---- B2: horizontal 5-tap at stride-2 -> down window (+ halo fold) ----
        // output pair c = 2tx, 2tx+1: taps t[4tx+2 .. 4tx+8]
#pragma unroll
        for (int r = ty; r < 20; r += 16) {
            if (tx < NL_B2) {
                const float* t = &s_t[r * CT + 4 * tx];
                float4 A = *(const float4*)t;
                float4 B = *(const float4*)(t + 4);
                float Cs = t[8];
                float o0 = (A.z + 4.f * A.w + 6.f * B.x + 4.f * B.y + B.z)
                         * (1.0f / 256.0f);
                float o1 = (B.x + 4.f * B.y + 6.f * B.z + 4.f * B.w + Cs)
                         * (1.0f / 256.0f);
                *(float2*)&s_dw[r][2 * tx] = make_float2(o0, o1);
                // halo columns: written by the lanes that own the source values
                if (ecol_lo) {
                    if (tx == 2) s_dw[r][0] = o0;   // [0]=[4]
                    if (tx == 1) s_dw[r][1] = o1;   // [1]=[3]
                }
                if (ecol_hi) {
                    if (tx == NL_B2 - 2) {          // owns cols TW/2, TW/2+1
                        s_dw[r][DWC - 2] = o1;      // [N2h+2]=[N2h+1]
                        s_dw[r][DWC - 1] = o0;      // [N2h+3]=[N2h]
                    }
                }
            }
        }
        __syncthreads();

        // ---- B3: write block-owned 16 x TW/2 down piece ----
        if constexpr (LVL < 2) {
            if (tx < TW / 2) {
                float* dn = img ? dn1 : dn0;
                dn[(size_t)((blockIdx.y << 4) + ty) * N2
                   + blockIdx.x * (TW / 2) + tx] = s_dw[ty + 2][tx + 2];
            }
        }

        // ---- C: horizontal up pass over down rows (linear, all blocks) ----
#pragma unroll
        for (int r = ty; r < 20; r += 16) {
            for (int q = tx; q < TW / 2 + 2; q += 32) {
                float a = s_dw[r][q], b = s_dw[r][q + 1], c = s_dw[r][q + 2];
                float e = 0.125f * a + 0.75f * b + 0.125f * c;  // even j=2q
                float o = 0.5f * (b + c);                        // odd j=2q+1
                *(float2*)&s_h[r][2 * q] = make_float2(e, o);
            }
        }
        __syncthreads();

        // ---- D: vertical up pass + diff (linear, all blocks) ----
#pragma unroll
        for (int i = ty; i < 36; i += 16) {
            int a, b, c; float w0, w1, w2;
            if (i & 1) { a = (i + 1) >> 1; b = (i + 3) >> 1; c = a;
                         w0 = 0.5f; w1 = 0.5f; w2 = 0.f; }
            else       { a = i >> 1; b = a + 1; c = a + 2;
                         w0 = 0.125f; w1 = 0.75f; w2 = 0.125f; }
            for (int q = tx; q < TW / 2 + 2; q += 32) {
                const int j = 2 * q;
                float2 ha = *(const float2*)&s_h[a][j];
                float2 hb = *(const float2*)&s_h[b][j];
                float2 hc = *(const float2*)&s_h[c][j];
                float2 cu = *(const float2*)&s_cur[i + 4][j + 6];
                float2 o;
                o.x = cu.x - (w0 * ha.x + w1 * hb.x + w2 * hc.x);
                o.y = cu.y - (w0 * ha.y + w1 * hb.y + w2 * hc.y);
                *(float2*)&s_df[img][i][j] = o;
            }
        }
        __syncthreads();
    }

    // ---- E: sobel |GX|+|GY| per image, |m0-m1|; flat item loop ----
    float val = 0.f;
    {
        const int rows_out = (blockIdx.y == gridDim.y - 1) ? 34 : 32;
        const int cols_out = ecol_hi ? TW + 2 : TW;
        for (int item = tid; item < 36 * STRIPS; item += 512) {
            const int row = item / STRIPS;
            const int c0 = (item - row * STRIPS) * 4;
            if (row >= rows_out) continue;
            float m0[4];
#pragma unroll
            for (int im = 0; im < 2; im++) {
                float t[6], v[6], u[6];
                {
                    const float4 a = *(const float4*)&s_df[im][row][c0];
                    const float2 b = *(const float2*)&s_df[im][row][c0 + 4];
                    t[0] = a.x; t[1] = a.y; t[2] = a.z; t[3] = a.w; t[4] = b.x; t[5] = b.y;
                }
#pragma unroll
                for (int j = 0; j < 6; j++) { v[j] = 2.f * t[j]; u[j] = 2.f * t[j]; }
                {
                    const float4 a = *(const float4*)&s_df[im][row + 1][c0];
                    const float2 b = *(const float2*)&s_df[im][row + 1][c0 + 4];
                    t[0] = a.x; t[1] = a.y; t[2] = a.z; t[3] = a.w; t[4] = b.x; t[5] = b.y;
                }
#pragma unroll
                for (int j = 0; j < 6; j++) v[j] += 4.f * t[j];
                {
                    const float4 a = *(const float4*)&s_df[im][row + 2][c0];
                    const float2 b = *(const float2*)&s_df[im][row + 2][c0 + 4];
                    t[0] = a.x; t[1] = a.y; t[2] = a.z; t[3] = a.w; t[4] = b.x; t[5] = b.y;
                }
#pragma unroll
                for (int j = 0; j < 6; j++) { v[j] += 2.f * t[j]; u[j] -= 2.f * t[j]; }
#pragma unroll
                for (int k = 0; k < 4; k++) {
                    float gx = v[k] - v[k + 2];
                    float gy = u[k] + 2.f * u[k + 1] + u[k + 2];
                    float m = fabsf(gx) + fabsf(gy);
                    if (im == 0) m0[k] = m;
                    else if (c0 + k < cols_out) val += fabsf(m0[k] - m);
                }
            }
        }
    }

    // ---- block reduction -> one double atomic per block ----
#pragma unroll
    for (int off = 16; off > 0; off >>= 1)
        val += __shfl_down_sync(0xffffffffu, val, off);
    if ((tid & 31) == 0) warpsum[tid >> 5] = val;
    __syncthreads();
    if (tid < 16) {
        float v = warpsum[tid];
#pragma unroll
        for (int off = 8; off > 0; off >>= 1)
            v += __shfl_down_sync(0xffffu, v, off);
        if (tid == 0) atomicAdd(&g_acc[LVL], (double)v);
    }
}

__global__ void finalize_kernel(float* __restrict__ out) {
    double l = g_acc[0] / ((double)PLANES * 514.0 * 514.0)
             + g_acc[1] / ((double)PLANES * 258.0 * 258.0)
             + g_acc[2] / ((double)PLANES * 130.0 * 130.0);
    out[0] = (float)l;
}

// -------------------------------------------------------------------------------
extern "C" void kernel_launch(void* const* d_in, const int* in_sizes, int n_in,
                              void* d_out, int out_size) {
    const float* inp = (const float*)d_in[0];
    const float* tgt = (const float*)d_in[1];
    // d_in[2] (gauss_kernel) is a fixed constant — baked into the kernels.
    float* out = (float*)d_out;

    zero_acc_kernel<<<1, 32>>>();

    lap_kernel<0><<<dim3(8, 16, PLANES), dim3(32, 16)>>>(inp, tgt);  // N=512, TW=64
    lap_kernel<1><<<dim3(4, 8, PLANES),  dim3(32, 16)>>>(inp, tgt);  // N=256, TW=64
    lap_kernel<2><<<dim3(4, 4, PLANES),  dim3(32, 16)>>>(inp, tgt);  // N=128, TW=32

    finalize_kernel<<<1, 1>>>(out);
}

// round 15
// speedup vs baseline: 1.7262x; 1.0175x over previous
#include <cuda_runtime.h>

#define PLANES 48  // B*C = 16*3

// ---------------- static device scratch (no allocations allowed) ----------------
__device__ float g_d1[2][PLANES * 256 * 256];  // level-0 downs == level-1 currents
__device__ float g_d2[2][PLANES * 128 * 128];  // level-1 downs == level-2 currents
__device__ double g_acc[3];                    // per-level |.| sums

// reflect index (numpy 'reflect'): valid for |p| well under n
__device__ __forceinline__ int refl(int p, int n) {
    p = (p < 0) ? -p : p;
    return (p >= n) ? (2 * n - 2 - p) : p;
}

__global__ void zero_acc_kernel() {
    if (threadIdx.x < 3) g_acc[threadIdx.x] = 0.0;
}

// -------------------------------------------------------------------------------
// lap_kernel<LVL>: fused down+up+diff+sobel+reduce in PADDED coordinates.
// block (32,16)=512 threads. Tile: 32 rows x 64 cols for ALL levels (R13 showed
// smaller tiles raise per-block overhead more than occupancy pays back).
// s_cur origin (oy0-6, ox0-8): -8 col origin makes interior phase-A float4-
// aligned. Down-window halo columns are written by the lanes that compute their
// source values (no extra barrier); halo rows folded in B1 for free.
// -------------------------------------------------------------------------------
template <int LVL>
__global__ __launch_bounds__(512, 4) void lap_kernel(const float* __restrict__ extA,
                                                     const float* __restrict__ extB) {
    constexpr int N  = (LVL == 0) ? 512 : (LVL == 1) ? 256 : 128;
    constexpr int N2 = N >> 1;
    constexpr int TW = 64;                     // tile cols
    constexpr int CT = TW + 16;                // s_cur cols (80)
    constexpr int DWC = TW / 2 + 4;            // s_dw cols (36)
    constexpr int DWP = DWC + 4;               // s_dw pitch (40)
    constexpr int HC = TW + 4;                 // s_h cols (68)
    constexpr int DFP = TW + 8;                // s_df pitch (72)
    constexpr int NL_B1 = CT / 4;              // B1 float4 lanes (20)
    constexpr int NL_B2 = (TW + 8) / 4;        // B2 pair lanes (18)
    constexpr int STRIPS = TW / 4 + 1;         // E strips per row (17)

    const int p = blockIdx.z;
    const float *cur0, *cur1;
    float *dn0 = nullptr, *dn1 = nullptr;
    if constexpr (LVL == 0) {
        cur0 = extA + (size_t)p * N * N;     cur1 = extB + (size_t)p * N * N;
        dn0 = g_d1[0] + (size_t)p * N2 * N2; dn1 = g_d1[1] + (size_t)p * N2 * N2;
    } else if constexpr (LVL == 1) {
        cur0 = g_d1[0] + (size_t)p * N * N;  cur1 = g_d1[1] + (size_t)p * N * N;
        dn0 = g_d2[0] + (size_t)p * N2 * N2; dn1 = g_d2[1] + (size_t)p * N2 * N2;
    } else {
        cur0 = g_d2[0] + (size_t)p * N * N;  cur1 = g_d2[1] + (size_t)p * N * N;
    }

    __shared__ __align__(16) float s_cur[43][CT];     // padded cur tile
    __shared__ __align__(16) float s_dw[20][DWP];     // down window (padded coarse)
    __shared__ __align__(16) float s_h[20][HC];       // horizontally upsampled rows
    __shared__ __align__(16) float s_df[2][36][DFP];  // diff tiles (also B scratch)
    __shared__ int rowoffT[43], colmapT[CT];
    __shared__ float warpsum[16];

    const int tx = threadIdx.x, ty = threadIdx.y;
    const int tid = ty * 32 + tx;
    const int oy0 = blockIdx.y * 32, ox0 = blockIdx.x * TW;
    const int crmin = (oy0 >> 1) - 2;   // padded coarse row origin of s_dw
    const int gr0p = oy0 - 6;           // padded fine row origin of s_cur
    const int gc0p = ox0 - 8;           // padded fine col origin (16B aligned)

    const bool interiorA = (gr0p >= 0) && (gr0p + 42 <= N - 1)
                        && (gc0p >= 0) && (gc0p + CT - 1 <= N - 1);
    const bool ecol_lo = (blockIdx.x == 0);
    const bool ecol_hi = (blockIdx.x == gridDim.x - 1);

    // ---- phase-A address tables (boundary blocks only) ----
    if (!interiorA) {
        if (tid < 43) rowoffT[tid] = refl(gr0p + tid, N) * N;
        else if (tid < 43 + CT) colmapT[tid - 43] = refl(gc0p + tid - 43, N);
        __syncthreads();
    }

    for (int img = 0; img < 2; img++) {
        const float* cur = img ? cur1 : cur0;
        float* s_t = &s_df[img][0][0];   // phase-B scratch (pitch CT), dead until D

        // ---- A: load padded cur tile 43 x CT into smem ----
        if (interiorA) {
#pragma unroll
            for (int r = ty; r < 43; r += 16) {
                const float* rp = cur + (gr0p + r) * N + gc0p;
                if (tx < NL_B1)
                    *(float4*)&s_cur[r][4 * tx] = *(const float4*)(rp + 4 * tx);
            }
        } else {
#pragma unroll
            for (int r = ty; r < 43; r += 16) {
                const int ro = rowoffT[r];
#pragma unroll
                for (int c = tx; c < CT; c += 32)
                    s_cur[r][c] = __ldg(&cur[ro + colmapT[c]]);
            }
        }
        __syncthreads();

        // ---- B1: vertical 5-tap at folded coarse rows (float4, all CT cols) ----
#pragma unroll
        for (int r = ty; r < 20; r += 16) {
            if (tx < NL_B1) {
                int cr = crmin + r;
                int src = (cr < 0) ? -cr : ((cr >= N2) ? 2 * N2 - 1 - cr : cr);
                const int fb = 2 * src + 4 - oy0;   // s_cur row of fine 2*src-2
                const int c4 = 4 * tx;
                float4 a0 = *(const float4*)&s_cur[fb + 0][c4];
                float4 a1 = *(const float4*)&s_cur[fb + 1][c4];
                float4 a2 = *(const float4*)&s_cur[fb + 2][c4];
                float4 a3 = *(const float4*)&s_cur[fb + 3][c4];
                float4 a4 = *(const float4*)&s_cur[fb + 4][c4];
                float4 o;
                o.x = a0.x + 4.f * (a1.x + a3.x) + 6.f * a2.x + a4.x;
                o.y = a0.y + 4.f * (a1.y + a3.y) + 6.f * a2.y + a4.y;
                o.z = a0.z + 4.f * (a1.z + a3.z) + 6.f * a2.z + a4.z;
                o.w = a0.w + 4.f * (a1.w + a3.w) + 6.f * a2.w + a4.w;
                *(float4*)&s_t[r * CT + c4] = o;
            }
        }
        __syncthreads();

        // ---- B2: horizontal 5-tap at stride-2 -> down window (+ halo fold) ----
        // output pair c = 2tx, 2tx+1: taps t[4tx+2 .. 4tx+8]
#pragma unroll
        for (int r = ty; r < 20; r += 16) {
            if (tx < NL_B2) {
                const float* t = &s_t[r * CT + 4 * tx];
                float4 A = *(const float4*)t;
                float4 B = *(const float4*)(t + 4);
                float Cs = t[8];
                float o0 = (A.z + 4.f * A.w + 6.f * B.x + 4.f * B.y + B.z)
                         * (1.0f / 256.0f);
                float o1 = (B.x + 4.f * B.y + 6.f * B.z + 4.f * B.w + Cs)
                         * (1.0f / 256.0f);
                *(float2*)&s_dw[r][2 * tx] = make_float2(o0, o1);
                // halo columns: written by the lanes that own the source values
                if (ecol_lo) {
                    if (tx == 2) s_dw[r][0] = o0;   // [0]=[4]
                    if (tx == 1) s_dw[r][1] = o1;   // [1]=[3]
                }
                if (ecol_hi) {
                    if (tx == NL_B2 - 2) {          // owns cols TW/2, TW/2+1
                        s_dw[r][DWC - 2] = o1;      // [N2h+2]=[N2h+1]
                        s_dw[r][DWC - 1] = o0;      // [N2h+3]=[N2h]
                    }
                }
            }
        }
        __syncthreads();

        // ---- B3: write block-owned 16 x TW/2 down piece ----
        if constexpr (LVL < 2) {
            float* dn = img ? dn1 : dn0;
            dn[(size_t)((blockIdx.y << 4) + ty) * N2
               + blockIdx.x * (TW / 2) + tx] = s_dw[ty + 2][tx + 2];
        }

        // ---- C: horizontal up pass over down rows (linear, all blocks) ----
#pragma unroll
        for (int r = ty; r < 20; r += 16) {
            for (int q = tx; q < TW / 2 + 2; q += 32) {
                float a = s_dw[r][q], b = s_dw[r][q + 1], c = s_dw[r][q + 2];
                float e = 0.125f * a + 0.75f * b + 0.125f * c;  // even j=2q
                float o = 0.5f * (b + c);                        // odd j=2q+1
                *(float2*)&s_h[r][2 * q] = make_float2(e, o);
            }
        }
        __syncthreads();

        // ---- D: vertical up pass + diff (linear, all blocks) ----
#pragma unroll
        for (int i = ty; i < 36; i += 16) {
            int a, b, c; float w0, w1, w2;
            if (i & 1) { a = (i + 1) >> 1; b = (i + 3) >> 1; c = a;
                         w0 = 0.5f; w1 = 0.5f; w2 = 0.f; }
            else       { a = i >> 1; b = a + 1; c = a + 2;
                         w0 = 0.125f; w1 = 0.75f; w2 = 0.125f; }
            for (int q = tx; q < TW / 2 + 2; q += 32) {
                const int j = 2 * q;
                float2 ha = *(const float2*)&s_h[a][j];
                float2 hb = *(const float2*)&s_h[b][j];
                float2 hc = *(const float2*)&s_h[c][j];
                float2 cu = *(const float2*)&s_cur[i + 4][j + 6];
                float2 o;
                o.x = cu.x - (w0 * ha.x + w1 * hb.x + w2 * hc.x);
                o.y = cu.y - (w0 * ha.y + w1 * hb.y + w2 * hc.y);
                *(float2*)&s_df[img][i][j] = o;
            }
        }
        __syncthreads();
    }

    // ---- E: sobel |GX|+|GY| per image, |m0-m1|; flat item loop ----
    float val = 0.f;
    {
        const int rows_out = (blockIdx.y == gridDim.y - 1) ? 34 : 32;
        const int cols_out = ecol_hi ? TW + 2 : TW;
        for (int item = tid; item < 36 * STRIPS; item += 512) {
            const int row = item / STRIPS;
            const int c0 = (item - row * STRIPS) * 4;
            if (row >= rows_out) continue;
            float m0[4];
#pragma unroll
            for (int im = 0; im < 2; im++) {
                float t[6], v[6], u[6];
                {
                    const float4 a = *(const float4*)&s_df[im][row][c0];
                    const float2 b = *(const float2*)&s_df[im][row][c0 + 4];
                    t[0] = a.x; t[1] = a.y; t[2] = a.z; t[3] = a.w; t[4] = b.x; t[5] = b.y;
                }
#pragma unroll
                for (int j = 0; j < 6; j++) { v[j] = 2.f * t[j]; u[j] = 2.f * t[j]; }
                {
                    const float4 a = *(const float4*)&s_df[im][row + 1][c0];
                    const float2 b = *(const float2*)&s_df[im][row + 1][c0 + 4];
                    t[0] = a.x; t[1] = a.y; t[2] = a.z; t[3] = a.w; t[4] = b.x; t[5] = b.y;
                }
#pragma unroll
                for (int j = 0; j < 6; j++) v[j] += 4.f * t[j];
                {
                    const float4 a = *(const float4*)&s_df[im][row + 2][c0];
                    const float2 b = *(const float2*)&s_df[im][row + 2][c0 + 4];
                    t[0] = a.x; t[1] = a.y; t[2] = a.z; t[3] = a.w; t[4] = b.x; t[5] = b.y;
                }
#pragma unroll
                for (int j = 0; j < 6; j++) { v[j] += 2.f * t[j]; u[j] -= 2.f * t[j]; }
#pragma unroll
                for (int k = 0; k < 4; k++) {
                    float gx = v[k] - v[k + 2];
                    float gy = u[k] + 2.f * u[k + 1] + u[k + 2];
                    float m = fabsf(gx) + fabsf(gy);
                    if (im == 0) m0[k] = m;
                    else if (c0 + k < cols_out) val += fabsf(m0[k] - m);
                }
            }
        }
    }

    // ---- block reduction -> one double atomic per block ----
#pragma unroll
    for (int off = 16; off > 0; off >>= 1)
        val += __shfl_down_sync(0xffffffffu, val, off);
    if ((tid & 31) == 0) warpsum[tid >> 5] = val;
    __syncthreads();
    if (tid < 16) {
        float v = warpsum[tid];
#pragma unroll
        for (int off = 8; off > 0; off >>= 1)
            v += __shfl_down_sync(0xffffu, v, off);
        if (tid == 0) atomicAdd(&g_acc[LVL], (double)v);
    }
}

__global__ void finalize_kernel(float* __restrict__ out) {
    double l = g_acc[0] / ((double)PLANES * 514.0 * 514.0)
             + g_acc[1] / ((double)PLANES * 258.0 * 258.0)
             + g_acc[2] / ((double)PLANES * 130.0 * 130.0);
    out[0] = (float)l;
}

// -------------------------------------------------------------------------------
extern "C" void kernel_launch(void* const* d_in, const int* in_sizes, int n_in,
                              void* d_out, int out_size) {
    const float* inp = (const float*)d_in[0];
    const float* tgt = (const float*)d_in[1];
    // d_in[2] (gauss_kernel) is a fixed constant — baked into the kernels.
    float* out = (float*)d_out;

    zero_acc_kernel<<<1, 32>>>();

    lap_kernel<0><<<dim3(8, 16, PLANES), dim3(32, 16)>>>(inp, tgt);  // N=512
    lap_kernel<1><<<dim3(4, 8, PLANES),  dim3(32, 16)>>>(inp, tgt);  // N=256
    lap_kernel<2><<<dim3(2, 4, PLANES),  dim3(32, 16)>>>(inp, tgt);  // N=128

    finalize_kernel<<<1, 1>>>(out);
}

// round 16
// speedup vs baseline: 1.8172x; 1.0527x over previous
#include <cuda_runtime.h>

#define PLANES 48  // B*C = 16*3

// ---------------- static device scratch (no allocations allowed) ----------------
__device__ float g_d1[2][PLANES * 256 * 256];  // level-0 downs == level-1 currents
__device__ float g_d2[2][PLANES * 128 * 128];  // level-1 downs == level-2 currents
__device__ double g_acc[3];                    // per-level |.| sums

// reflect index (numpy 'reflect'): valid for |p| well under n
__device__ __forceinline__ int refl(int p, int n) {
    p = (p < 0) ? -p : p;
    return (p >= n) ? (2 * n - 2 - p) : p;
}

__global__ void zero_acc_kernel() {
    if (threadIdx.x < 3) g_acc[threadIdx.x] = 0.0;
}

// -------------------------------------------------------------------------------
// lap_kernel<LVL>: fused down+up+diff+sobel+reduce in PADDED coordinates.
// block (32,16)=512 threads; 32x64 tile of the (N+2)x(N+2) loss grid.
// B1+B2 fused in registers via warp shuffles (row r is produced & consumed by
// warp ty throughout B/C, so B1->B2->C need no block barriers — only syncwarp).
// 3 full barriers per image: after A, after C (covers B3+D), after D.
// -------------------------------------------------------------------------------
template <int LVL>
__global__ __launch_bounds__(512, 4) void lap_kernel(const float* __restrict__ extA,
                                                     const float* __restrict__ extB) {
    constexpr int N  = (LVL == 0) ? 512 : (LVL == 1) ? 256 : 128;
    constexpr int N2 = N >> 1;
    constexpr int TW = 64;                     // tile cols
    constexpr int CT = TW + 16;                // s_cur cols (80)
    constexpr int DWC = TW / 2 + 4;            // s_dw cols (36)
    constexpr int DWP = DWC + 4;               // s_dw pitch (40)
    constexpr int HC = TW + 4;                 // s_h cols (68)
    constexpr int DFP = TW + 8;                // s_df pitch (72)
    constexpr int NL_B1 = CT / 4;              // B1 float4 lanes (20)
    constexpr int NL_B2 = (TW + 8) / 4;        // B2 pair lanes (18)
    constexpr int STRIPS = TW / 4 + 1;         // E strips per row (17)

    const int p = blockIdx.z;
    const float *cur0, *cur1;
    float *dn0 = nullptr, *dn1 = nullptr;
    if constexpr (LVL == 0) {
        cur0 = extA + (size_t)p * N * N;     cur1 = extB + (size_t)p * N * N;
        dn0 = g_d1[0] + (size_t)p * N2 * N2; dn1 = g_d1[1] + (size_t)p * N2 * N2;
    } else if constexpr (LVL == 1) {
        cur0 = g_d1[0] + (size_t)p * N * N;  cur1 = g_d1[1] + (size_t)p * N * N;
        dn0 = g_d2[0] + (size_t)p * N2 * N2; dn1 = g_d2[1] + (size_t)p * N2 * N2;
    } else {
        cur0 = g_d2[0] + (size_t)p * N * N;  cur1 = g_d2[1] + (size_t)p * N * N;
    }

    __shared__ __align__(16) float s_cur[43][CT];     // padded cur tile
    __shared__ __align__(16) float s_dw[20][DWP];     // down window (padded coarse)
    __shared__ __align__(16) float s_h[20][HC];       // horizontally upsampled rows
    __shared__ __align__(16) float s_df[2][36][DFP];  // diff tiles
    __shared__ int rowoffT[43], colmapT[CT];
    __shared__ float warpsum[16];

    const int tx = threadIdx.x, ty = threadIdx.y;
    const int tid = ty * 32 + tx;
    const int oy0 = blockIdx.y * 32, ox0 = blockIdx.x * TW;
    const int crmin = (oy0 >> 1) - 2;   // padded coarse row origin of s_dw
    const int gr0p = oy0 - 6;           // padded fine row origin of s_cur
    const int gc0p = ox0 - 8;           // padded fine col origin (16B aligned)

    const bool interiorA = (gr0p >= 0) && (gr0p + 42 <= N - 1)
                        && (gc0p >= 0) && (gc0p + CT - 1 <= N - 1);
    const bool ecol_lo = (blockIdx.x == 0);
    const bool ecol_hi = (blockIdx.x == gridDim.x - 1);

    // ---- phase-A address tables (boundary blocks only) ----
    if (!interiorA) {
        if (tid < 43) rowoffT[tid] = refl(gr0p + tid, N) * N;
        else if (tid < 43 + CT) colmapT[tid - 43] = refl(gc0p + tid - 43, N);
        __syncthreads();
    }

    for (int img = 0; img < 2; img++) {
        const float* cur = img ? cur1 : cur0;

        // ---- A: load padded cur tile 43 x CT into smem ----
        if (interiorA) {
            for (int item = tid; item < 43 * NL_B1; item += 512) {
                const int r = item / NL_B1;
                const int c = (item - r * NL_B1) * 4;
                *(float4*)&s_cur[r][c] =
                    *(const float4*)(cur + (size_t)(gr0p + r) * N + gc0p + c);
            }
        } else {
#pragma unroll
            for (int r = ty; r < 43; r += 16) {
                const int ro = rowoffT[r];
#pragma unroll
                for (int c = tx; c < CT; c += 32)
                    s_cur[r][c] = __ldg(&cur[ro + colmapT[c]]);
            }
        }
        __syncthreads();

        // ---- B (fused B1+B2 via shuffles) + C, all warp-local per row ----
#pragma unroll
        for (int r = ty; r < 20; r += 16) {
            int cr = crmin + r;
            int src = (cr < 0) ? -cr : ((cr >= N2) ? 2 * N2 - 1 - cr : cr);
            const int fb = 2 * src + 4 - oy0;      // s_cur row of fine 2*src-2
            const int c4 = 4 * min(tx, NL_B1 - 1); // lanes >=20 duplicate lane 19
            // B1: vertical 5-tap [1,4,6,4,1], result in registers
            float4 a0 = *(const float4*)&s_cur[fb + 0][c4];
            float4 a1 = *(const float4*)&s_cur[fb + 1][c4];
            float4 a2 = *(const float4*)&s_cur[fb + 2][c4];
            float4 a3 = *(const float4*)&s_cur[fb + 3][c4];
            float4 a4 = *(const float4*)&s_cur[fb + 4][c4];
            float4 t;
            t.x = a0.x + 4.f * (a1.x + a3.x) + 6.f * a2.x + a4.x;
            t.y = a0.y + 4.f * (a1.y + a3.y) + 6.f * a2.y + a4.y;
            t.z = a0.z + 4.f * (a1.z + a3.z) + 6.f * a2.z + a4.z;
            t.w = a0.w + 4.f * (a1.w + a3.w) + 6.f * a2.w + a4.w;
            // B2: horizontal 5-tap at stride-2; cross-lane taps via shfl
            float Bx = __shfl_down_sync(0xffffffffu, t.x, 1);
            float By = __shfl_down_sync(0xffffffffu, t.y, 1);
            float Bz = __shfl_down_sync(0xffffffffu, t.z, 1);
            float Bw = __shfl_down_sync(0xffffffffu, t.w, 1);
            float Cs = __shfl_down_sync(0xffffffffu, t.x, 2);
            if (tx < NL_B2) {
                float o0 = (t.z + 4.f * t.w + 6.f * Bx + 4.f * By + Bz)
                         * (1.0f / 256.0f);
                float o1 = (Bx + 4.f * By + 6.f * Bz + 4.f * Bw + Cs)
                         * (1.0f / 256.0f);
                *(float2*)&s_dw[r][2 * tx] = make_float2(o0, o1);
                // halo columns: written by the lanes that own the source values
                if (ecol_lo) {
                    if (tx == 2) s_dw[r][0] = o0;   // [0]=[4]
                    if (tx == 1) s_dw[r][1] = o1;   // [1]=[3]
                }
                if (ecol_hi && tx == NL_B2 - 2) {   // owns cols 32,33
                    s_dw[r][DWC - 2] = o1;          // [34]=[33]
                    s_dw[r][DWC - 1] = o0;          // [35]=[32]
                }
            }
            __syncwarp();
            // C: horizontal up pass for row r (reads only row r, same warp)
            for (int q = tx; q < TW / 2 + 2; q += 32) {
                float a = s_dw[r][q], b = s_dw[r][q + 1], c = s_dw[r][q + 2];
                float e = 0.125f * a + 0.75f * b + 0.125f * c;  // even j=2q
                float o = 0.5f * (b + c);                        // odd j=2q+1
                *(float2*)&s_h[r][2 * q] = make_float2(e, o);
            }
        }
        __syncthreads();

        // ---- B3: write block-owned 16 x TW/2 down piece (cross-warp read OK now) ----
        if constexpr (LVL < 2) {
            float* dn = img ? dn1 : dn0;
            dn[(size_t)((blockIdx.y << 4) + ty) * N2
               + blockIdx.x * (TW / 2) + tx] = s_dw[ty + 2][tx + 2];
        }

        // ---- D: vertical up pass + diff ----
#pragma unroll
        for (int i = ty; i < 36; i += 16) {
            int a, b, c; float w0, w1, w2;
            if (i & 1) { a = (i + 1) >> 1; b = (i + 3) >> 1; c = a;
                         w0 = 0.5f; w1 = 0.5f; w2 = 0.f; }
            else       { a = i >> 1; b = a + 1; c = a + 2;
                         w0 = 0.125f; w1 = 0.75f; w2 = 0.125f; }
            for (int q = tx; q < TW / 2 + 2; q += 32) {
                const int j = 2 * q;
                float2 ha = *(const float2*)&s_h[a][j];
                float2 hb = *(const float2*)&s_h[b][j];
                float2 hc = *(const float2*)&s_h[c][j];
                float2 cu = *(const float2*)&s_cur[i + 4][j + 6];
                float2 o;
                o.x = cu.x - (w0 * ha.x + w1 * hb.x + w2 * hc.x);
                o.y = cu.y - (w0 * ha.y + w1 * hb.y + w2 * hc.y);
                *(float2*)&s_df[img][i][j] = o;
            }
        }
        __syncthreads();
    }

    // ---- E: sobel |GX|+|GY| per image, |m0-m1|; flat item loop ----
    float val = 0.f;
    {
        const int rows_out = (blockIdx.y == gridDim.y - 1) ? 34 : 32;
        const int cols_out = ecol_hi ? TW + 2 : TW;
        for (int item = tid; item < 36 * STRIPS; item += 512) {
            const int row = item / STRIPS;
            const int c0 = (item - row * STRIPS) * 4;
            if (row >= rows_out) continue;
            float m0[4];
#pragma unroll
            for (int im = 0; im < 2; im++) {
                float t[6], v[6], u[6];
                {
                    const float4 a = *(const float4*)&s_df[im][row][c0];
                    const float2 b = *(const float2*)&s_df[im][row][c0 + 4];
                    t[0] = a.x; t[1] = a.y; t[2] = a.z; t[3] = a.w; t[4] = b.x; t[5] = b.y;
                }
#pragma unroll
                for (int j = 0; j < 6; j++) { v[j] = 2.f * t[j]; u[j] = 2.f * t[j]; }
                {
                    const float4 a = *(const float4*)&s_df[im][row + 1][c0];
                    const float2 b = *(const float2*)&s_df[im][row + 1][c0 + 4];
                    t[0] = a.x; t[1] = a.y; t[2] = a.z; t[3] = a.w; t[4] = b.x; t[5] = b.y;
                }
#pragma unroll
                for (int j = 0; j < 6; j++) v[j] += 4.f * t[j];
                {
                    const float4 a = *(const float4*)&s_df[im][row + 2][c0];
                    const float2 b = *(const float2*)&s_df[im][row + 2][c0 + 4];
                    t[0] = a.x; t[1] = a.y; t[2] = a.z; t[3] = a.w; t[4] = b.x; t[5] = b.y;
                }
#pragma unroll
                for (int j = 0; j < 6; j++) { v[j] += 2.f * t[j]; u[j] -= 2.f * t[j]; }
#pragma unroll
                for (int k = 0; k < 4; k++) {
                    float gx = v[k] - v[k + 2];
                    float gy = u[k] + 2.f * u[k + 1] + u[k + 2];
                    float m = fabsf(gx) + fabsf(gy);
                    if (im == 0) m0[k] = m;
                    else if (c0 + k < cols_out) val += fabsf(m0[k] - m);
                }
            }
        }
    }

    // ---- block reduction -> one double atomic per block ----
#pragma unroll
    for (int off = 16; off > 0; off >>= 1)
        val += __shfl_down_sync(0xffffffffu, val, off);
    if ((tid & 31) == 0) warpsum[tid >> 5] = val;
    __syncthreads();
    if (tid < 16) {
        float v = warpsum[tid];
#pragma unroll
        for (int off = 8; off > 0; off >>= 1)
            v += __shfl_down_sync(0xffffu, v, off);
        if (tid == 0) atomicAdd(&g_acc[LVL], (double)v);
    }
}

__global__ void finalize_kernel(float* __restrict__ out) {
    double l = g_acc[0] / ((double)PLANES * 514.0 * 514.0)
             + g_acc[1] / ((double)PLANES * 258.0 * 258.0)
             + g_acc[2] / ((double)PLANES * 130.0 * 130.0);
    out[0] = (float)l;
}

// -------------------------------------------------------------------------------
extern "C" void kernel_launch(void* const* d_in, const int* in_sizes, int n_in,
                              void* d_out, int out_size) {
    const float* inp = (const float*)d_in[0];
    const float* tgt = (const float*)d_in[1];
    // d_in[2] (gauss_kernel) is a fixed constant — baked into the kernels.
    float* out = (float*)d_out;

    zero_acc_kernel<<<1, 32>>>();

    lap_kernel<0><<<dim3(8, 16, PLANES), dim3(32, 16)>>>(inp, tgt);  // N=512
    lap_kernel<1><<<dim3(4, 8, PLANES),  dim3(32, 16)>>>(inp, tgt);  // N=256
    lap_kernel<2><<<dim3(2, 4, PLANES),  dim3(32, 16)>>>(inp, tgt);  // N=128

    finalize_kernel<<<1, 1>>>(out);
}

// round 17
// speedup vs baseline: 1.9486x; 1.0723x over previous
#include <cuda_runtime.h>

#define PLANES 48  // B*C = 16*3

// ---------------- static device scratch (no allocations allowed) ----------------
__device__ float g_d1[2][PLANES * 256 * 256];  // level-0 downs == level-1 currents
__device__ float g_d2[2][PLANES * 128 * 128];  // level-1 downs == level-2 currents
__device__ double g_acc[3];                    // per-level |.| sums

// reflect index (numpy 'reflect'): valid for |p| well under n
__device__ __forceinline__ int refl(int p, int n) {
    p = (p < 0) ? -p : p;
    return (p >= n) ? (2 * n - 2 - p) : p;
}

__global__ void zero_acc_kernel() {
    if (threadIdx.x < 3) g_acc[threadIdx.x] = 0.0;
}

// -------------------------------------------------------------------------------
// lap_kernel<LVL>: fused down+up+diff+sobel+reduce in PADDED coordinates.
// block (32,16)=512 threads; 32x64 tile of the (N+2)x(N+2) loss grid.
// B1+B2 fused in registers via warp shuffles; the down-plane write happens
// straight from B's registers (no B3 phase). D processes row PAIRS per warp:
// 3 shared h-loads serve 2 output rows. 3 full barriers per image.
// -------------------------------------------------------------------------------
template <int LVL>
__global__ __launch_bounds__(512, 4) void lap_kernel(const float* __restrict__ extA,
                                                     const float* __restrict__ extB) {
    constexpr int N  = (LVL == 0) ? 512 : (LVL == 1) ? 256 : 128;
    constexpr int N2 = N >> 1;
    constexpr int TW = 64;                     // tile cols
    constexpr int CT = TW + 16;                // s_cur cols (80)
    constexpr int DWC = TW / 2 + 4;            // s_dw cols (36)
    constexpr int DWP = DWC + 4;               // s_dw pitch (40)
    constexpr int HC = TW + 4;                 // s_h cols (68)
    constexpr int DFP = TW + 8;                // s_df pitch (72)
    constexpr int NL_B1 = CT / 4;              // B1 float4 lanes (20)
    constexpr int NL_B2 = (TW + 8) / 4;        // B2 pair lanes (18)
    constexpr int STRIPS = TW / 4 + 1;         // E strips per row (17)

    const int p = blockIdx.z;
    const float *cur0, *cur1;
    float *dn0 = nullptr, *dn1 = nullptr;
    if constexpr (LVL == 0) {
        cur0 = extA + (size_t)p * N * N;     cur1 = extB + (size_t)p * N * N;
        dn0 = g_d1[0] + (size_t)p * N2 * N2; dn1 = g_d1[1] + (size_t)p * N2 * N2;
    } else if constexpr (LVL == 1) {
        cur0 = g_d1[0] + (size_t)p * N * N;  cur1 = g_d1[1] + (size_t)p * N * N;
        dn0 = g_d2[0] + (size_t)p * N2 * N2; dn1 = g_d2[1] + (size_t)p * N2 * N2;
    } else {
        cur0 = g_d2[0] + (size_t)p * N * N;  cur1 = g_d2[1] + (size_t)p * N * N;
    }

    __shared__ __align__(16) float s_cur[43][CT];     // padded cur tile
    __shared__ __align__(16) float s_dw[20][DWP];     // down window (padded coarse)
    __shared__ __align__(16) float s_h[20][HC];       // horizontally upsampled rows
    __shared__ __align__(16) float s_df[2][36][DFP];  // diff tiles
    __shared__ int rowoffT[43], colmapT[CT];
    __shared__ float warpsum[16];

    const int tx = threadIdx.x, ty = threadIdx.y;
    const int tid = ty * 32 + tx;
    const int oy0 = blockIdx.y * 32, ox0 = blockIdx.x * TW;
    const int crmin = (oy0 >> 1) - 2;   // padded coarse row origin of s_dw
    const int gr0p = oy0 - 6;           // padded fine row origin of s_cur
    const int gc0p = ox0 - 8;           // padded fine col origin (16B aligned)

    const bool interiorA = (gr0p >= 0) && (gr0p + 42 <= N - 1)
                        && (gc0p >= 0) && (gc0p + CT - 1 <= N - 1);
    const bool ecol_lo = (blockIdx.x == 0);
    const bool ecol_hi = (blockIdx.x == gridDim.x - 1);

    // ---- phase-A address tables (boundary blocks only) ----
    if (!interiorA) {
        if (tid < 43) rowoffT[tid] = refl(gr0p + tid, N) * N;
        else if (tid < 43 + CT) colmapT[tid - 43] = refl(gc0p + tid - 43, N);
        __syncthreads();
    }

    for (int img = 0; img < 2; img++) {
        const float* cur = img ? cur1 : cur0;
        float* dn = img ? dn1 : dn0;

        // ---- A: load padded cur tile 43 x CT into smem ----
        if (interiorA) {
            for (int item = tid; item < 43 * NL_B1; item += 512) {
                const int r = item / NL_B1;
                const int c = (item - r * NL_B1) * 4;
                *(float4*)&s_cur[r][c] =
                    *(const float4*)(cur + (size_t)(gr0p + r) * N + gc0p + c);
            }
        } else {
#pragma unroll
            for (int r = ty; r < 43; r += 16) {
                const int ro = rowoffT[r];
#pragma unroll
                for (int c = tx; c < CT; c += 32)
                    s_cur[r][c] = __ldg(&cur[ro + colmapT[c]]);
            }
        }
        __syncthreads();

        // ---- B (fused B1+B2 via shuffles, down write from registers) + C ----
#pragma unroll
        for (int r = ty; r < 20; r += 16) {
            int cr = crmin + r;
            int src = (cr < 0) ? -cr : ((cr >= N2) ? 2 * N2 - 1 - cr : cr);
            const int fb = 2 * src + 4 - oy0;      // s_cur row of fine 2*src-2
            const int c4 = 4 * min(tx, NL_B1 - 1); // lanes >=20 broadcast lane 19
            // B1: vertical 5-tap [1,4,6,4,1], result in registers
            float4 a0 = *(const float4*)&s_cur[fb + 0][c4];
            float4 a1 = *(const float4*)&s_cur[fb + 1][c4];
            float4 a2 = *(const float4*)&s_cur[fb + 2][c4];
            float4 a3 = *(const float4*)&s_cur[fb + 3][c4];
            float4 a4 = *(const float4*)&s_cur[fb + 4][c4];
            float4 t;
            t.x = a0.x + 4.f * (a1.x + a3.x) + 6.f * a2.x + a4.x;
            t.y = a0.y + 4.f * (a1.y + a3.y) + 6.f * a2.y + a4.y;
            t.z = a0.z + 4.f * (a1.z + a3.z) + 6.f * a2.z + a4.z;
            t.w = a0.w + 4.f * (a1.w + a3.w) + 6.f * a2.w + a4.w;
            // B2: horizontal 5-tap at stride-2; cross-lane taps via shfl
            float Bx = __shfl_down_sync(0xffffffffu, t.x, 1);
            float By = __shfl_down_sync(0xffffffffu, t.y, 1);
            float Bz = __shfl_down_sync(0xffffffffu, t.z, 1);
            float Bw = __shfl_down_sync(0xffffffffu, t.w, 1);
            float Cs = __shfl_down_sync(0xffffffffu, t.x, 2);
            if (tx < NL_B2) {
                float o0 = (t.z + 4.f * t.w + 6.f * Bx + 4.f * By + Bz)
                         * (1.0f / 256.0f);
                float o1 = (Bx + 4.f * By + 6.f * Bz + 4.f * Bw + Cs)
                         * (1.0f / 256.0f);
                *(float2*)&s_dw[r][2 * tx] = make_float2(o0, o1);
                // down-plane write straight from registers (was phase B3):
                // lane tx owns dw cols 2tx,2tx+1 = piece cols 2tx-2,2tx-1
                if constexpr (LVL < 2) {
                    if (r >= 2 && r < 18 && tx >= 1 && tx <= 16) {
                        *(float2*)&dn[(size_t)((blockIdx.y << 4) + r - 2) * N2
                                      + (blockIdx.x << 5) + 2 * tx - 2]
                            = make_float2(o0, o1);
                    }
                }
                // halo columns: written by the lanes that own the source values
                if (ecol_lo) {
                    if (tx == 2) s_dw[r][0] = o0;   // [0]=[4]
                    if (tx == 1) s_dw[r][1] = o1;   // [1]=[3]
                }
                if (ecol_hi && tx == NL_B2 - 2) {   // owns cols 32,33
                    s_dw[r][DWC - 2] = o1;          // [34]=[33]
                    s_dw[r][DWC - 1] = o0;          // [35]=[32]
                }
            }
            __syncwarp();
            // C: horizontal up pass for row r (reads only row r, same warp)
            for (int q = tx; q < TW / 2 + 2; q += 32) {
                float a = s_dw[r][q], b = s_dw[r][q + 1], c = s_dw[r][q + 2];
                float e = 0.125f * a + 0.75f * b + 0.125f * c;  // even j=2q
                float o = 0.5f * (b + c);                        // odd j=2q+1
                *(float2*)&s_h[r][2 * q] = make_float2(e, o);
            }
        }
        __syncthreads();

        // ---- D: vertical up pass + diff; row PAIRS per warp ----
        // pair pp -> rows 2pp (even: h[pp..pp+2], .125/.75/.125)
        //            and 2pp+1 (odd: h[pp+1..pp+2], .5/.5)
#pragma unroll
        for (int pp = ty; pp < 18; pp += 16) {
            for (int q = tx; q < TW / 2 + 2; q += 32) {
                const int j = 2 * q;
                float2 h0 = *(const float2*)&s_h[pp][j];
                float2 h1 = *(const float2*)&s_h[pp + 1][j];
                float2 h2 = *(const float2*)&s_h[pp + 2][j];
                float2 cu0 = *(const float2*)&s_cur[2 * pp + 4][j + 6];
                float2 cu1 = *(const float2*)&s_cur[2 * pp + 5][j + 6];
                float2 d0, d1;
                d0.x = cu0.x - (0.125f * h0.x + 0.75f * h1.x + 0.125f * h2.x);
                d0.y = cu0.y - (0.125f * h0.y + 0.75f * h1.y + 0.125f * h2.y);
                d1.x = cu1.x - 0.5f * (h1.x + h2.x);
                d1.y = cu1.y - 0.5f * (h1.y + h2.y);
                *(float2*)&s_df[img][2 * pp][j] = d0;
                *(float2*)&s_df[img][2 * pp + 1][j] = d1;
            }
        }
        __syncthreads();
    }

    // ---- E: sobel |GX|+|GY| per image, |m0-m1|; flat item loop ----
    float val = 0.f;
    {
        const int rows_out = (blockIdx.y == gridDim.y - 1) ? 34 : 32;
        const int cols_out = ecol_hi ? TW + 2 : TW;
        for (int item = tid; item < 36 * STRIPS; item += 512) {
            const int row = item / STRIPS;
            const int c0 = (item - row * STRIPS) * 4;
            if (row >= rows_out) continue;
            float m0[4];
#pragma unroll
            for (int im = 0; im < 2; im++) {
                float t[6], v[6], u[6];
                {
                    const float4 a = *(const float4*)&s_df[im][row][c0];
                    const float2 b = *(const float2*)&s_df[im][row][c0 + 4];
                    t[0] = a.x; t[1] = a.y; t[2] = a.z; t[3] = a.w; t[4] = b.x; t[5] = b.y;
                }
#pragma unroll
                for (int j = 0; j < 6; j++) { v[j] = 2.f * t[j]; u[j] = 2.f * t[j]; }
                {
                    const float4 a = *(const float4*)&s_df[im][row + 1][c0];
                    const float2 b = *(const float2*)&s_df[im][row + 1][c0 + 4];
                    t[0] = a.x; t[1] = a.y; t[2] = a.z; t[3] = a.w; t[4] = b.x; t[5] = b.y;
                }
#pragma unroll
                for (int j = 0; j < 6; j++) v[j] += 4.f * t[j];
                {
                    const float4 a = *(const float4*)&s_df[im][row + 2][c0];
                    const float2 b = *(const float2*)&s_df[im][row + 2][c0 + 4];
                    t[0] = a.x; t[1] = a.y; t[2] = a.z; t[3] = a.w; t[4] = b.x; t[5] = b.y;
                }
#pragma unroll
                for (int j = 0; j < 6; j++) { v[j] += 2.f * t[j]; u[j] -= 2.f * t[j]; }
#pragma unroll
                for (int k = 0; k < 4; k++) {
                    float gx = v[k] - v[k + 2];
                    float gy = u[k] + 2.f * u[k + 1] + u[k + 2];
                    float m = fabsf(gx) + fabsf(gy);
                    if (im == 0) m0[k] = m;
                    else if (c0 + k < cols_out) val += fabsf(m0[k] - m);
                }
            }
        }
    }

    // ---- block reduction -> one double atomic per block ----
#pragma unroll
    for (int off = 16; off > 0; off >>= 1)
        val += __shfl_down_sync(0xffffffffu, val, off);
    if ((tid & 31) == 0) warpsum[tid >> 5] = val;
    __syncthreads();
    if (tid < 16) {
        float v = warpsum[tid];
#pragma unroll
        for (int off = 8; off > 0; off >>= 1)
            v += __shfl_down_sync(0xffffu, v, off);
        if (tid == 0) atomicAdd(&g_acc[LVL], (double)v);
    }
}

__global__ void finalize_kernel(float* __restrict__ out) {
    double l = g_acc[0] / ((double)PLANES * 514.0 * 514.0)
             + g_acc[1] / ((double)PLANES * 258.0 * 258.0)
             + g_acc[2] / ((double)PLANES * 130.0 * 130.0);
    out[0] = (float)l;
}

// -------------------------------------------------------------------------------
extern "C" void kernel_launch(void* const* d_in, const int* in_sizes, int n_in,
                              void* d_out, int out_size) {
    const float* inp = (const float*)d_in[0];
    const float* tgt = (const float*)d_in[1];
    // d_in[2] (gauss_kernel) is a fixed constant — baked into the kernels.
    float* out = (float*)d_out;

    zero_acc_kernel<<<1, 32>>>();

    lap_kernel<0><<<dim3(8, 16, PLANES), dim3(32, 16)>>>(inp, tgt);  // N=512
    lap_kernel<1><<<dim3(4, 8, PLANES),  dim3(32, 16)>>>(inp, tgt);  // N=256
    lap_kernel<2><<<dim3(2, 4, PLANES),  dim3(32, 16)>>>(inp, tgt);  // N=128

    finalize_kernel<<<1, 1>>>(out);
}